// round 9
// baseline (speedup 1.0000x reference)
#include <cuda_runtime.h>
#include <math.h>

#define BB 4
#define SS 1024
#define DM 1280
#define NH 16
#define DK 80
#define GR 5
#define CPG 256

// ---- scratch (device globals; no allocations allowed) ----
__device__ float g_q[(size_t)BB*NH*SS*DK];   // column-permuted (perm8)
__device__ float g_k[(size_t)BB*NH*SS*DK];   // column-permuted (perm8)
__device__ float g_v[(size_t)BB*NH*SS*DK];   // linear
// pre-split bf16 words (hi/lo), pre-permuted for m16n8k16 fragments
__device__ unsigned g_ah[(size_t)BB*SS*(DM/2)];
__device__ unsigned g_al[(size_t)BB*SS*(DM/2)];
__device__ unsigned g_bh[(size_t)DM*(DM/2)];
__device__ unsigned g_bl[(size_t)DM*(DM/2)];

// ---- helpers ----
__device__ __forceinline__ float f2tf32(float x) {
    unsigned u;
    asm("cvt.rna.tf32.f32 %0, %1;" : "=r"(u) : "f"(x));
    return __uint_as_float(u);
}
__device__ __forceinline__ void mma_tf32(float d[4], const unsigned a[4], const unsigned b[2]) {
    asm volatile(
        "mma.sync.aligned.m16n8k8.row.col.f32.tf32.tf32.f32 "
        "{%0,%1,%2,%3}, {%4,%5,%6,%7}, {%8,%9}, {%0,%1,%2,%3};\n"
        : "+f"(d[0]), "+f"(d[1]), "+f"(d[2]), "+f"(d[3])
        : "r"(a[0]), "r"(a[1]), "r"(a[2]), "r"(a[3]), "r"(b[0]), "r"(b[1]));
}
__device__ __forceinline__ void mma_bf16(float d[4], const unsigned a[4], const unsigned b[2]) {
    asm volatile(
        "mma.sync.aligned.m16n8k16.row.col.f32.bf16.bf16.f32 "
        "{%0,%1,%2,%3}, {%4,%5,%6,%7}, {%8,%9}, {%0,%1,%2,%3};\n"
        : "+f"(d[0]), "+f"(d[1]), "+f"(d[2]), "+f"(d[3])
        : "r"(a[0]), "r"(a[1]), "r"(a[2]), "r"(a[3]), "r"(b[0]), "r"(b[1]));
}
__device__ __forceinline__ unsigned pack_bf16(float hi, float lo) {
    unsigned r;
    asm("cvt.rn.bf16x2.f32 %0, %1, %2;" : "=r"(r) : "f"(hi), "f"(lo));
    return r;
}
__device__ __forceinline__ float bf_lo(unsigned w) { return __uint_as_float(w << 16); }
__device__ __forceinline__ float bf_hi(unsigned w) { return __uint_as_float(w & 0xffff0000u); }

__device__ __forceinline__ unsigned smem_u32(const void* p) {
    return (unsigned)__cvta_generic_to_shared(p);
}
__device__ __forceinline__ void cp16(unsigned s, const void* g) {
    asm volatile("cp.async.cg.shared.global [%0], [%1], 16;" :: "r"(s), "l"(g));
}
__device__ __forceinline__ void cp_commit() { asm volatile("cp.async.commit_group;"); }
template<int N> __device__ __forceinline__ void cp_wait() {
    asm volatile("cp.async.wait_group %0;" :: "n"(N));
}
// column pairing within 8-group: (t, t+4) -> adjacent (2t, 2t+1)
__device__ __forceinline__ int perm8(int c) {
    return (c & ~7) | ((c & 3) << 1) | ((c >> 2) & 1);
}

// ============================================================
// Kernel 0: pre-split Wo into bf16 hi/lo permuted word arrays
// ============================================================
__global__ __launch_bounds__(256) void wsplit_kernel(const float* __restrict__ Wo)
{
    int i = blockIdx.x * 256 + threadIdx.x;
    if (i >= DM * (DM/2)) return;
    int n = i / (DM/2), w = i % (DM/2);
    float x0 = Wo[(size_t)n*DM + 2*w];
    float x1 = Wo[(size_t)n*DM + 2*w + 1];
    unsigned h = pack_bf16(x1, x0);
    unsigned l = pack_bf16(x1 - bf_hi(h), x0 - bf_lo(h));
    int pos = (w >> 3)*8 + perm8(w & 7);
    g_bh[(size_t)n*(DM/2) + pos] = h;
    g_bl[(size_t)n*(DM/2) + pos] = l;
}

// ============================================================
// Kernel 1: channel shuffle + per-head QKV projections
// Q/K written column-permuted (perm8); 1/sqrt(dk) folded into Q
// ============================================================
#define XS 84
#define QKV_SMEM_FLOATS (128*XS + 80*XS + 80)

__global__ __launch_bounds__(256) void qkv_kernel(
    const float* __restrict__ src,
    const float* __restrict__ Wq, const float* __restrict__ bq,
    const float* __restrict__ Wk, const float* __restrict__ bk,
    const float* __restrict__ Wv, const float* __restrict__ bv)
{
    extern __shared__ float qsm[];
    float* sX = qsm;              // [128][84]
    float* sW = sX + 128*XS;      // [80][84]
    float* sb = sW + 80*XS;       // [80]

    const int b = blockIdx.z, h = blockIdx.y, s0 = blockIdx.x * 128;
    const int tid = threadIdx.x;
    const int warp = tid >> 5, lane = tid & 31;
    const int g = lane >> 2, t = lane & 3;
    const int wr = warp * 16;

    #pragma unroll
    for (int p = 0; p < 10; p++) {
        int idx = tid + p*256;
        int r = idx / 20, q = idx % 20;
        int j = q / 4, m = q % 4;
        float4 v = *(const float4*)&src[((size_t)b*SS + s0 + r)*DM + j*CPG + 16*h + m*4];
        int kbase = (m*4)*5 + j;
        sX[r*XS + kbase     ] = f2tf32(v.x);
        sX[r*XS + kbase + 5 ] = f2tf32(v.y);
        sX[r*XS + kbase + 10] = f2tf32(v.z);
        sX[r*XS + kbase + 15] = f2tf32(v.w);
    }
    __syncthreads();

    unsigned qa[10][4];
    #pragma unroll
    for (int ks = 0; ks < 10; ks++) {
        qa[ks][0] = __float_as_uint(sX[(wr + g    )*XS + ks*8 + t    ]);
        qa[ks][1] = __float_as_uint(sX[(wr + g + 8)*XS + ks*8 + t    ]);
        qa[ks][2] = __float_as_uint(sX[(wr + g    )*XS + ks*8 + t + 4]);
        qa[ks][3] = __float_as_uint(sX[(wr + g + 8)*XS + ks*8 + t + 4]);
    }

    const float* Ws[3] = {Wq, Wk, Wv};
    const float* bs[3] = {bq, bk, bv};
    float* outs[3] = {g_q, g_k, g_v};
    const float scl = rsqrtf((float)DK);

    const int pc0 = ((2*t & 3) << 1) | ((2*t) >> 2);
    const int pc1 = (((2*t+1) & 3) << 1) | ((2*t+1) >> 2);

    for (int pj = 0; pj < 3; pj++) {
        const float s = (pj == 0) ? scl : 1.f;
        __syncthreads();
        for (int i = tid; i < 1600; i += 256) {
            int e = i / 20, k = (i % 20) * 4;
            float4 w = *(const float4*)&Ws[pj][h*DK*DK + e*DK + k];
            float4 wr4 = make_float4(f2tf32(w.x*s), f2tf32(w.y*s), f2tf32(w.z*s), f2tf32(w.w*s));
            *(float4*)&sW[e*XS + k] = wr4;
        }
        if (tid < DK) sb[tid] = bs[pj][h*DK + tid] * s;
        __syncthreads();

        float acc[10][4];
        #pragma unroll
        for (int nt = 0; nt < 10; nt++)
            #pragma unroll
            for (int j = 0; j < 4; j++) acc[nt][j] = 0.f;

        #pragma unroll
        for (int ks = 0; ks < 10; ks++) {
            #pragma unroll
            for (int nt = 0; nt < 10; nt++) {
                unsigned bb[2];
                bb[0] = __float_as_uint(sW[(nt*8 + g)*XS + ks*8 + t    ]);
                bb[1] = __float_as_uint(sW[(nt*8 + g)*XS + ks*8 + t + 4]);
                mma_tf32(acc[nt], qa[ks], bb);
            }
        }

        float* outp = outs[pj] + (((size_t)b*NH + h)*SS + s0) * DK;
        #pragma unroll
        for (int nt = 0; nt < 10; nt++) {
            int c = nt*8 + 2*t;
            float b0 = sb[c], b1 = sb[c + 1];
            float v00 = f2tf32(acc[nt][0] + b0), v01 = f2tf32(acc[nt][1] + b1);
            float v10 = f2tf32(acc[nt][2] + b0), v11 = f2tf32(acc[nt][3] + b1);
            if (pj < 2) {   // permuted scalar stores (Q, K)
                outp[(size_t)(wr + g    )*DK + nt*8 + pc0] = v00;
                outp[(size_t)(wr + g    )*DK + nt*8 + pc1] = v01;
                outp[(size_t)(wr + g + 8)*DK + nt*8 + pc0] = v10;
                outp[(size_t)(wr + g + 8)*DK + nt*8 + pc1] = v11;
            } else {        // linear float2 stores (V)
                *(float2*)&outp[(size_t)(wr + g    )*DK + c] = make_float2(v00, v01);
                *(float2*)&outp[(size_t)(wr + g + 8)*DK + c] = make_float2(v10, v11);
            }
        }
    }
}

// ============================================================
// Kernel 2: flash attention, tf32 mma, 8 warps x 16 q-rows
// occ 2 (112.6 KB): no sP (P A-frags via warp shuffles),
// Q/K pre-permuted in gmem (paired LDS.64 frags),
// K single-buffered, V double-buffered.
// ============================================================
#define QP 88
#define KP 88
#define VP 88
#define A_OFF_Q 0
#define A_OFF_K (128*QP)
#define A_OFF_V (A_OFF_K + 64*KP)
#define ATTN_SMEM_FLOATS (A_OFF_V + 2*64*VP)   // 28160 fl = 112.6 KB

__device__ __forceinline__ void issueQK(const float* Qb, const float* Kb,
                                        float* sQ, float* sK, int q0, int tid)
{
    #pragma unroll
    for (int p = 0; p < 10; p++) {
        int c = tid + p*256;
        int r = c / 20, seg = c % 20;
        cp16(smem_u32(sQ + r*QP + seg*4), Qb + (size_t)(q0 + r)*DK + seg*4);
    }
    #pragma unroll
    for (int p = 0; p < 5; p++) {
        int c = tid + p*256;
        int r = c / 20, seg = c % 20;
        cp16(smem_u32(sK + r*KP + seg*4), Kb + (size_t)r*DK + seg*4);
    }
    cp_commit();
}
__device__ __forceinline__ void issueK(const float* Kb, float* sK, int kt, int tid)
{
    #pragma unroll
    for (int p = 0; p < 5; p++) {
        int c = tid + p*256;
        int r = c / 20, seg = c % 20;
        cp16(smem_u32(sK + r*KP + seg*4), Kb + (size_t)(kt + r)*DK + seg*4);
    }
    cp_commit();
}
__device__ __forceinline__ void issueV(const float* Vb, float* sV, int kt, int tid)
{
    #pragma unroll
    for (int p = 0; p < 5; p++) {
        int c = tid + p*256;
        int r = c / 20, seg = c % 20;
        cp16(smem_u32(sV + r*VP + seg*4), Vb + (size_t)(kt + r)*DK + seg*4);
    }
    cp_commit();
}

__global__ __launch_bounds__(256, 2) void attn_kernel()
{
    extern __shared__ float sm[];
    float* sQ = sm + A_OFF_Q;
    float* sK = sm + A_OFF_K;

    const int b = blockIdx.z, h = blockIdx.y, q0 = blockIdx.x * 128;
    const int tid = threadIdx.x;
    const int warp = tid >> 5, lane = tid & 31;
    const int g = lane >> 2, t = lane & 3;
    const int wr = warp * 16;

    const size_t base = ((size_t)b*NH + h) * SS * DK;
    const float* Qb = g_q + base;     // pre-scaled, permuted
    const float* Kb = g_k + base;     // permuted
    const float* Vb = g_v + base;     // linear

    issueQK(Qb, Kb, sQ, sK, q0, tid);             // group 1: Q + K0
    issueV(Vb, sm + A_OFF_V, 0, tid);             // group 2: V0

    float O[10][4];
    #pragma unroll
    for (int nt = 0; nt < 10; nt++)
        #pragma unroll
        for (int j = 0; j < 4; j++) O[nt][j] = 0.f;
    float m0 = -1e30f, m1 = -1e30f, l0 = 0.f, l1 = 0.f;

    const int lane_lo = (lane & 28) | (t >> 1);
    const int lane_hi = lane_lo + 2;
    const bool odd = t & 1;

    for (int tt = 0; tt < SS/64; tt++) {
        float* sV = sm + A_OFF_V + (tt & 1) * 64*VP;

        cp_wait<1>();        // Q + K(tt) complete (V(tt) may be pending)
        __syncthreads();

        // ---- scores: paired LDS.64 for both Q and K fragments ----
        float sc[8][4];
        #pragma unroll
        for (int nt = 0; nt < 8; nt++)
            #pragma unroll
            for (int j = 0; j < 4; j++) sc[nt][j] = 0.f;

        #pragma unroll
        for (int ks = 0; ks < 10; ks++) {
            unsigned qa[4];
            float2 qlo = *(const float2*)&sQ[(wr + g    )*QP + ks*8 + 2*t];
            float2 qhi = *(const float2*)&sQ[(wr + g + 8)*QP + ks*8 + 2*t];
            qa[0] = __float_as_uint(qlo.x);
            qa[2] = __float_as_uint(qlo.y);
            qa[1] = __float_as_uint(qhi.x);
            qa[3] = __float_as_uint(qhi.y);
            #pragma unroll
            for (int nt = 0; nt < 8; nt++) {
                float2 kv = *(const float2*)&sK[(nt*8 + g)*KP + ks*8 + 2*t];
                unsigned bb[2];
                bb[0] = __float_as_uint(kv.x);
                bb[1] = __float_as_uint(kv.y);
                mma_tf32(sc[nt], qa, bb);
            }
        }
        __syncthreads();     // all warps done with sK
        if (tt + 1 < SS/64)
            issueK(Kb, sK, (tt+1)*64, tid);       // group: K(tt+1)

        // ---- online softmax ----
        float mx0 = -1e30f, mx1 = -1e30f;
        #pragma unroll
        for (int nt = 0; nt < 8; nt++) {
            mx0 = fmaxf(mx0, fmaxf(sc[nt][0], sc[nt][1]));
            mx1 = fmaxf(mx1, fmaxf(sc[nt][2], sc[nt][3]));
        }
        #pragma unroll
        for (int msk = 1; msk <= 2; msk <<= 1) {
            mx0 = fmaxf(mx0, __shfl_xor_sync(0xffffffffu, mx0, msk));
            mx1 = fmaxf(mx1, __shfl_xor_sync(0xffffffffu, mx1, msk));
        }
        float mn0 = fmaxf(m0, mx0), mn1 = fmaxf(m1, mx1);
        float a0 = __expf(m0 - mn0), a1 = __expf(m1 - mn1);
        m0 = mn0; m1 = mn1;

        float sum0 = 0.f, sum1 = 0.f;
        #pragma unroll
        for (int nt = 0; nt < 8; nt++) {
            float e0 = __expf(sc[nt][0] - m0);
            float e1 = __expf(sc[nt][1] - m0);
            float e2 = __expf(sc[nt][2] - m1);
            float e3 = __expf(sc[nt][3] - m1);
            sum0 += e0 + e1;
            sum1 += e2 + e3;
            sc[nt][0] = f2tf32(e0); sc[nt][1] = f2tf32(e1);
            sc[nt][2] = f2tf32(e2); sc[nt][3] = f2tf32(e3);
        }
        #pragma unroll
        for (int msk = 1; msk <= 2; msk <<= 1) {
            sum0 += __shfl_xor_sync(0xffffffffu, sum0, msk);
            sum1 += __shfl_xor_sync(0xffffffffu, sum1, msk);
        }
        l0 = l0*a0 + sum0;
        l1 = l1*a1 + sum1;

        #pragma unroll
        for (int nt = 0; nt < 10; nt++) {
            O[nt][0] *= a0; O[nt][1] *= a0;
            O[nt][2] *= a1; O[nt][3] *= a1;
        }

        if (tt + 1 < SS/64) cp_wait<1>();   // V(tt) done (K(tt+1) pending)
        else                cp_wait<0>();
        __syncthreads();
        if (tt + 1 < SS/64)
            issueV(Vb, sm + A_OFF_V + ((tt+1)&1)*64*VP, (tt+1)*64, tid);

        // ---- PV: P A-frags via shuffles (D-frag -> A-frag permute) ----
        #pragma unroll
        for (int ks = 0; ks < 8; ks++) {
            float r0a = __shfl_sync(0xffffffffu, sc[ks][0], lane_lo);
            float r0b = __shfl_sync(0xffffffffu, sc[ks][1], lane_lo);
            float r1a = __shfl_sync(0xffffffffu, sc[ks][2], lane_lo);
            float r1b = __shfl_sync(0xffffffffu, sc[ks][3], lane_lo);
            float r2a = __shfl_sync(0xffffffffu, sc[ks][0], lane_hi);
            float r2b = __shfl_sync(0xffffffffu, sc[ks][1], lane_hi);
            float r3a = __shfl_sync(0xffffffffu, sc[ks][2], lane_hi);
            float r3b = __shfl_sync(0xffffffffu, sc[ks][3], lane_hi);
            unsigned pa[4];
            pa[0] = __float_as_uint(odd ? r0b : r0a);
            pa[1] = __float_as_uint(odd ? r1b : r1a);
            pa[2] = __float_as_uint(odd ? r2b : r2a);
            pa[3] = __float_as_uint(odd ? r3b : r3a);
            #pragma unroll
            for (int nt = 0; nt < 10; nt++) {
                unsigned bb[2];
                bb[0] = __float_as_uint(sV[(ks*8 + t    )*VP + nt*8 + g]);
                bb[1] = __float_as_uint(sV[(ks*8 + t + 4)*VP + nt*8 + g]);
                mma_tf32(O[nt], pa, bb);
            }
        }
    }

    // ---- epilogue: normalize + pre-split bf16 write ----
    float inv0 = 1.f / l0, inv1 = 1.f / l1;
    int s0r = q0 + wr + g, s1r = s0r + 8;
    #pragma unroll
    for (int nt = 0; nt < 10; nt++) {
        int w = nt*4 + t;
        int pos = h*(DK/2) + (w >> 3)*8 + perm8(w & 7);
        float v00 = O[nt][0]*inv0, v01 = O[nt][1]*inv0;
        float v10 = O[nt][2]*inv1, v11 = O[nt][3]*inv1;
        unsigned h0 = pack_bf16(v01, v00);
        unsigned l0w = pack_bf16(v01 - bf_hi(h0), v00 - bf_lo(h0));
        unsigned h1 = pack_bf16(v11, v10);
        unsigned l1w = pack_bf16(v11 - bf_hi(h1), v10 - bf_lo(h1));
        size_t r0 = ((size_t)b*SS + s0r)*(DM/2) + pos;
        size_t r1 = ((size_t)b*SS + s1r)*(DM/2) + pos;
        g_ah[r0] = h0;  g_al[r0] = l0w;
        g_ah[r1] = h1;  g_al[r1] = l1w;
    }
}

// ============================================================
// Kernel 3: out = A @ Wo^T + bo from pre-split bf16 words
// 64x128 tiles (640 CTAs: no 2-wave tail), k-chunks of 32
// ============================================================
#define GS 24
#define ASZ (64*GS)
#define BSZ (128*GS)
#define GEMM_SMEM_U32 (4*ASZ + 4*BSZ)   // 72 KB

__device__ __forceinline__ void gemm_issue(unsigned* gsm, int m0, int n0, int kc, int tid)
{
    const int buf = kc & 1;
    unsigned* AH = gsm + buf*ASZ;
    unsigned* AL = gsm + 2*ASZ + buf*ASZ;
    unsigned* BH = gsm + 4*ASZ + buf*BSZ;
    unsigned* BL = gsm + 4*ASZ + 2*BSZ + buf*BSZ;
    {
        int r = tid >> 2, seg = tid & 3;
        const size_t off = (size_t)(m0 + r)*(DM/2) + kc*16 + seg*4;
        cp16(smem_u32(AH + r*GS + seg*4), g_ah + off);
        cp16(smem_u32(AL + r*GS + seg*4), g_al + off);
    }
    #pragma unroll
    for (int p = 0; p < 2; p++) {
        int idx = tid + p*256;
        int r = idx >> 2, seg = idx & 3;
        const size_t off = (size_t)(n0 + r)*(DM/2) + kc*16 + seg*4;
        cp16(smem_u32(BH + r*GS + seg*4), g_bh + off);
        cp16(smem_u32(BL + r*GS + seg*4), g_bl + off);
    }
    cp_commit();
}

__global__ __launch_bounds__(256, 2) void out_gemm(
    const float* __restrict__ bo, float* __restrict__ out)
{
    extern __shared__ unsigned gsm[];

    const int m0 = blockIdx.y * 64, n0 = blockIdx.x * 128;
    const int tid = threadIdx.x;
    const int warp = tid >> 5, lane = tid & 31;
    const int g = lane >> 2, t = lane & 3;
    const int wm = warp >> 2, wn = warp & 3;   // 2 x 4 warps, 32x32 tiles

    float acc[2][4][4];
    #pragma unroll
    for (int mt = 0; mt < 2; mt++)
        #pragma unroll
        for (int nt = 0; nt < 4; nt++)
            #pragma unroll
            for (int j = 0; j < 4; j++) acc[mt][nt][j] = 0.f;

    gemm_issue(gsm, m0, n0, 0, tid);
    gemm_issue(gsm, m0, n0, 1, tid);

    for (int kc = 0; kc < DM/32; kc++) {
        if (kc + 1 < DM/32) cp_wait<1>();
        else                cp_wait<0>();
        __syncthreads();

        const int buf = kc & 1;
        const unsigned* AH = gsm + buf*ASZ;
        const unsigned* AL = gsm + 2*ASZ + buf*ASZ;
        const unsigned* BH = gsm + 4*ASZ + buf*BSZ;
        const unsigned* BL = gsm + 4*ASZ + 2*BSZ + buf*BSZ;

        #pragma unroll
        for (int kk = 0; kk < 2; kk++) {
            unsigned fbh[4][2], fbl[4][2];
            #pragma unroll
            for (int nt = 0; nt < 4; nt++) {
                int br = wn*32 + nt*8 + g;
                uint2 xh = *(const uint2*)&BH[br*GS + kk*8 + 2*t];
                uint2 xl = *(const uint2*)&BL[br*GS + kk*8 + 2*t];
                fbh[nt][0] = xh.x; fbh[nt][1] = xh.y;
                fbl[nt][0] = xl.x; fbl[nt][1] = xl.y;
            }
            #pragma unroll
            for (int mt = 0; mt < 2; mt++) {
                int mr = wm*32 + mt*16 + g;
                uint2 alo = *(const uint2*)&AH[ mr     *GS + kk*8 + 2*t];
                uint2 ahi = *(const uint2*)&AH[(mr + 8)*GS + kk*8 + 2*t];
                uint2 llo = *(const uint2*)&AL[ mr     *GS + kk*8 + 2*t];
                uint2 lhi = *(const uint2*)&AL[(mr + 8)*GS + kk*8 + 2*t];
                unsigned fah[4] = {alo.x, ahi.x, alo.y, ahi.y};
                unsigned fal[4] = {llo.x, lhi.x, llo.y, lhi.y};
                #pragma unroll
                for (int nt = 0; nt < 4; nt++) {
                    mma_bf16(acc[mt][nt], fah, fbh[nt]);
                    mma_bf16(acc[mt][nt], fah, fbl[nt]);
                    mma_bf16(acc[mt][nt], fal, fbh[nt]);
                }
            }
        }
        __syncthreads();
        if (kc + 2 < DM/32)
            gemm_issue(gsm, m0, n0, kc + 2, tid);
    }

    #pragma unroll
    for (int mt = 0; mt < 2; mt++) {
        int r0 = m0 + wm*32 + mt*16 + g;
        #pragma unroll
        for (int nt = 0; nt < 4; nt++) {
            int c0 = n0 + wn*32 + nt*8 + 2*t;
            float2 b2 = *(const float2*)&bo[c0];
            float2 v0 = make_float2(acc[mt][nt][0] + b2.x, acc[mt][nt][1] + b2.y);
            float2 v1 = make_float2(acc[mt][nt][2] + b2.x, acc[mt][nt][3] + b2.y);
            *(float2*)&out[(size_t)r0*DM + c0] = v0;
            *(float2*)&out[(size_t)(r0 + 8)*DM + c0] = v1;
        }
    }
}

// ============================================================
extern "C" void kernel_launch(void* const* d_in, const int* in_sizes, int n_in,
                              void* d_out, int out_size)
{
    const float* src = (const float*)d_in[0];
    const float* Wq = (const float*)d_in[3];
    const float* bq = (const float*)d_in[4];
    const float* Wk = (const float*)d_in[5];
    const float* bk = (const float*)d_in[6];
    const float* Wv = (const float*)d_in[7];
    const float* bv = (const float*)d_in[8];
    const float* Wo = (const float*)d_in[9];
    const float* bo = (const float*)d_in[10];
    float* out = (float*)d_out;

    const int smem_qkv  = QKV_SMEM_FLOATS * (int)sizeof(float);
    const int smem_attn = ATTN_SMEM_FLOATS * (int)sizeof(float);
    const int smem_gemm = GEMM_SMEM_U32 * (int)sizeof(unsigned);
    cudaFuncSetAttribute(qkv_kernel, cudaFuncAttributeMaxDynamicSharedMemorySize, smem_qkv);
    cudaFuncSetAttribute(attn_kernel, cudaFuncAttributeMaxDynamicSharedMemorySize, smem_attn);
    cudaFuncSetAttribute(out_gemm, cudaFuncAttributeMaxDynamicSharedMemorySize, smem_gemm);

    wsplit_kernel<<<(DM*(DM/2) + 255)/256, 256>>>(Wo);
    qkv_kernel<<<dim3(SS/128, NH, BB), 256, smem_qkv>>>(src, Wq, bq, Wk, bk, Wv, bv);
    attn_kernel<<<dim3(SS/128, NH, BB), 256, smem_attn>>>();
    out_gemm<<<dim3(DM/128, (BB*SS)/64), 256, smem_gemm>>>(bo, out);
}

// round 10
// speedup vs baseline: 1.5005x; 1.5005x over previous
#include <cuda_runtime.h>
#include <math.h>

#define BB 4
#define SS 1024
#define DM 1280
#define NH 16
#define DK 80
#define GR 5
#define CPG 256

// ---- scratch (device globals; no allocations allowed) ----
__device__ float g_q[(size_t)BB*NH*SS*DK];
__device__ float g_k[(size_t)BB*NH*SS*DK];
__device__ float g_v[(size_t)BB*NH*SS*DK];
__device__ float g_att[(size_t)BB*SS*DM];   // tf32-rounded, perm8 cols
__device__ float g_wo[(size_t)DM*DM];       // tf32-rounded, perm8 cols

// ---- helpers ----
__device__ __forceinline__ float f2tf32(float x) {
    unsigned u;
    asm("cvt.rna.tf32.f32 %0, %1;" : "=r"(u) : "f"(x));
    return __uint_as_float(u);
}
__device__ __forceinline__ void mma_tf32(float d[4], const unsigned a[4], const unsigned b[2]) {
    asm volatile(
        "mma.sync.aligned.m16n8k8.row.col.f32.tf32.tf32.f32 "
        "{%0,%1,%2,%3}, {%4,%5,%6,%7}, {%8,%9}, {%0,%1,%2,%3};\n"
        : "+f"(d[0]), "+f"(d[1]), "+f"(d[2]), "+f"(d[3])
        : "r"(a[0]), "r"(a[1]), "r"(a[2]), "r"(a[3]), "r"(b[0]), "r"(b[1]));
}
__device__ __forceinline__ unsigned smem_u32(const void* p) {
    return (unsigned)__cvta_generic_to_shared(p);
}
__device__ __forceinline__ void cp16(unsigned s, const void* g) {
    asm volatile("cp.async.cg.shared.global [%0], [%1], 16;" :: "r"(s), "l"(g));
}
__device__ __forceinline__ void cp_commit() { asm volatile("cp.async.commit_group;"); }
template<int N> __device__ __forceinline__ void cp_wait() {
    asm volatile("cp.async.wait_group %0;" :: "n"(N));
}
// column pairing within 8-group: (t, t+4) -> adjacent (2t, 2t+1)
__device__ __forceinline__ int perm8(int c) {
    return (c & ~7) | ((c & 3) << 1) | ((c >> 2) & 1);
}

// ============================================================
// Kernel 0: round Wo to tf32 and store with perm8 column layout
// ============================================================
__global__ __launch_bounds__(256) void wo_round_kernel(const float* __restrict__ Wo)
{
    int i = blockIdx.x * 256 + threadIdx.x;    // over DM*DM/4 float4s
    if (i >= DM * (DM/4)) return;
    int n = i / (DM/4), k4 = (i % (DM/4)) * 4;
    float4 v = *(const float4*)&Wo[(size_t)n*DM + k4];
    int blk = k4 & ~7, off = k4 & 7;           // off = 0 or 4
    float* dst = g_wo + (size_t)n*DM + blk;
    dst[perm8(off    )] = f2tf32(v.x);
    dst[perm8(off + 1)] = f2tf32(v.y);
    dst[perm8(off + 2)] = f2tf32(v.z);
    dst[perm8(off + 3)] = f2tf32(v.w);
}

// ============================================================
// Kernel 1: channel shuffle + per-head QKV projections
// (R8 version; 1/sqrt(dk) folded into Wq/bq; linear outputs)
// ============================================================
#define XS 84
#define QKV_SMEM_FLOATS (128*XS + 80*XS + 80)

__global__ __launch_bounds__(256) void qkv_kernel(
    const float* __restrict__ src,
    const float* __restrict__ Wq, const float* __restrict__ bq,
    const float* __restrict__ Wk, const float* __restrict__ bk,
    const float* __restrict__ Wv, const float* __restrict__ bv)
{
    extern __shared__ float qsm[];
    float* sX = qsm;              // [128][84]
    float* sW = sX + 128*XS;      // [80][84]
    float* sb = sW + 80*XS;       // [80]

    const int b = blockIdx.z, h = blockIdx.y, s0 = blockIdx.x * 128;
    const int tid = threadIdx.x;
    const int warp = tid >> 5, lane = tid & 31;
    const int g = lane >> 2, t = lane & 3;
    const int wr = warp * 16;

    #pragma unroll
    for (int p = 0; p < 10; p++) {
        int idx = tid + p*256;
        int r = idx / 20, q = idx % 20;
        int j = q / 4, m = q % 4;
        float4 v = *(const float4*)&src[((size_t)b*SS + s0 + r)*DM + j*CPG + 16*h + m*4];
        int kbase = (m*4)*5 + j;
        sX[r*XS + kbase     ] = f2tf32(v.x);
        sX[r*XS + kbase + 5 ] = f2tf32(v.y);
        sX[r*XS + kbase + 10] = f2tf32(v.z);
        sX[r*XS + kbase + 15] = f2tf32(v.w);
    }
    __syncthreads();

    unsigned qa[10][4];
    #pragma unroll
    for (int ks = 0; ks < 10; ks++) {
        qa[ks][0] = __float_as_uint(sX[(wr + g    )*XS + ks*8 + t    ]);
        qa[ks][1] = __float_as_uint(sX[(wr + g + 8)*XS + ks*8 + t    ]);
        qa[ks][2] = __float_as_uint(sX[(wr + g    )*XS + ks*8 + t + 4]);
        qa[ks][3] = __float_as_uint(sX[(wr + g + 8)*XS + ks*8 + t + 4]);
    }

    const float* Ws[3] = {Wq, Wk, Wv};
    const float* bs[3] = {bq, bk, bv};
    float* outs[3] = {g_q, g_k, g_v};
    const float scl = rsqrtf((float)DK);

    for (int pj = 0; pj < 3; pj++) {
        const float s = (pj == 0) ? scl : 1.f;
        __syncthreads();
        for (int i = tid; i < 1600; i += 256) {
            int e = i / 20, k = (i % 20) * 4;
            float4 w = *(const float4*)&Ws[pj][h*DK*DK + e*DK + k];
            float4 wr4 = make_float4(f2tf32(w.x*s), f2tf32(w.y*s), f2tf32(w.z*s), f2tf32(w.w*s));
            *(float4*)&sW[e*XS + k] = wr4;
        }
        if (tid < DK) sb[tid] = bs[pj][h*DK + tid] * s;
        __syncthreads();

        float acc[10][4];
        #pragma unroll
        for (int nt = 0; nt < 10; nt++)
            #pragma unroll
            for (int j = 0; j < 4; j++) acc[nt][j] = 0.f;

        #pragma unroll
        for (int ks = 0; ks < 10; ks++) {
            #pragma unroll
            for (int nt = 0; nt < 10; nt++) {
                unsigned bb[2];
                bb[0] = __float_as_uint(sW[(nt*8 + g)*XS + ks*8 + t    ]);
                bb[1] = __float_as_uint(sW[(nt*8 + g)*XS + ks*8 + t + 4]);
                mma_tf32(acc[nt], qa[ks], bb);
            }
        }

        float* outp = outs[pj] + (((size_t)b*NH + h)*SS + s0) * DK;
        #pragma unroll
        for (int nt = 0; nt < 10; nt++) {
            int c = nt*8 + 2*t;
            float b0 = sb[c], b1 = sb[c + 1];
            float2 v0 = make_float2(f2tf32(acc[nt][0] + b0), f2tf32(acc[nt][1] + b1));
            float2 v1 = make_float2(f2tf32(acc[nt][2] + b0), f2tf32(acc[nt][3] + b1));
            *(float2*)&outp[(size_t)(wr + g    )*DK + c] = v0;
            *(float2*)&outp[(size_t)(wr + g + 8)*DK + c] = v1;
        }
    }
}

// ============================================================
// Kernel 2: flash attention, tf32 mma (R8 version)
// 256-row q tiles, 8 warps x 32 rows, K single-buf, V double-buf,
// per-warp P region. Epilogue writes tf32-rounded perm8 floats.
// ============================================================
#define QP 88
#define KP 84
#define VP 88
#define PPW 72
#define A_OFF_Q 0
#define A_OFF_K (256*QP)
#define A_OFF_V (A_OFF_K + 64*KP)
#define A_OFF_P (A_OFF_V + 2*64*VP)
#define ATTN_SMEM_FLOATS (A_OFF_P + 8*32*PPW)    // 225 KB

__device__ __forceinline__ void issueK(const float* Kb, float* sK, int kt, int tid)
{
    #pragma unroll
    for (int p = 0; p < 5; p++) {
        int c = tid + p*256;
        int r = c / 20, seg = c % 20;
        cp16(smem_u32(sK + r*KP + seg*4), Kb + (size_t)(kt + r)*DK + seg*4);
    }
    cp_commit();
}
__device__ __forceinline__ void issueV(const float* Vb, float* sV, int kt, int tid)
{
    #pragma unroll
    for (int p = 0; p < 5; p++) {
        int c = tid + p*256;
        int r = c / 20, seg = c % 20;
        cp16(smem_u32(sV + r*VP + seg*4), Vb + (size_t)(kt + r)*DK + seg*4);
    }
    cp_commit();
}

__global__ __launch_bounds__(256) void attn_kernel()
{
    extern __shared__ float sm[];
    float* sQ = sm + A_OFF_Q;
    float* sK = sm + A_OFF_K;

    const int b = blockIdx.z, h = blockIdx.y, q0 = blockIdx.x * 256;
    const int tid = threadIdx.x;
    const int warp = tid >> 5, lane = tid & 31;
    const int g = lane >> 2, t = lane & 3;
    const int wr = warp * 32;
    float* sP = sm + A_OFF_P + warp * 32 * PPW;   // warp-private

    const size_t base = ((size_t)b*NH + h) * SS * DK;
    const float* Qb = g_q + base;     // pre-scaled, tf32-rounded
    const float* Kb = g_k + base;
    const float* Vb = g_v + base;

    // stage Q (column-paired): 5120 float4 pieces
    #pragma unroll
    for (int p = 0; p < 20; p++) {
        int idx = tid + p*256;
        int r = idx / 20, q4 = idx % 20;
        float4 v = *(const float4*)&Qb[(size_t)(q0 + r)*DK + q4*4];
        int k = q4*4;
        sQ[r*QP + perm8(k    )] = v.x;
        sQ[r*QP + perm8(k + 1)] = v.y;
        sQ[r*QP + perm8(k + 2)] = v.z;
        sQ[r*QP + perm8(k + 3)] = v.w;
    }
    issueK(Kb, sK, 0, tid);                       // group K0
    issueV(Vb, sm + A_OFF_V, 0, tid);             // group V0

    float O[2][10][4];
    #pragma unroll
    for (int mt = 0; mt < 2; mt++)
        #pragma unroll
        for (int nt = 0; nt < 10; nt++)
            #pragma unroll
            for (int j = 0; j < 4; j++) O[mt][nt][j] = 0.f;
    float mM[2][2], lL[2][2];
    #pragma unroll
    for (int mt = 0; mt < 2; mt++) {
        mM[mt][0] = mM[mt][1] = -1e30f;
        lL[mt][0] = lL[mt][1] = 0.f;
    }

    const int pc0 = ((2*t & 3) << 1) | ((2*t) >> 2);
    const int pc1 = (((2*t+1) & 3) << 1) | ((2*t+1) >> 2);

    for (int tt = 0; tt < SS/64; tt++) {
        float* sV = sm + A_OFF_V + (tt & 1) * 64*VP;

        cp_wait<1>();        // K(tt) done (V(tt) may be pending)
        __syncthreads();

        float sc[2][8][4];
        #pragma unroll
        for (int mt = 0; mt < 2; mt++)
            #pragma unroll
            for (int nt = 0; nt < 8; nt++)
                #pragma unroll
                for (int j = 0; j < 4; j++) sc[mt][nt][j] = 0.f;

        #pragma unroll
        for (int ks = 0; ks < 10; ks++) {
            unsigned qa2[2][4];
            #pragma unroll
            for (int mt = 0; mt < 2; mt++) {
                float2 qlo = *(const float2*)&sQ[(wr + mt*16 + g    )*QP + ks*8 + 2*t];
                float2 qhi = *(const float2*)&sQ[(wr + mt*16 + g + 8)*QP + ks*8 + 2*t];
                qa2[mt][0] = __float_as_uint(qlo.x);
                qa2[mt][2] = __float_as_uint(qlo.y);
                qa2[mt][1] = __float_as_uint(qhi.x);
                qa2[mt][3] = __float_as_uint(qhi.y);
            }
            #pragma unroll
            for (int nt = 0; nt < 8; nt++) {
                unsigned bb[2];
                bb[0] = __float_as_uint(sK[(nt*8 + g)*KP + ks*8 + t    ]);
                bb[1] = __float_as_uint(sK[(nt*8 + g)*KP + ks*8 + t + 4]);
                mma_tf32(sc[0][nt], qa2[0], bb);
                mma_tf32(sc[1][nt], qa2[1], bb);
            }
        }
        __syncthreads();
        if (tt + 1 < SS/64)
            issueK(Kb, sK, (tt+1)*64, tid);

        #pragma unroll
        for (int mt = 0; mt < 2; mt++) {
            float mx0 = -1e30f, mx1 = -1e30f;
            #pragma unroll
            for (int nt = 0; nt < 8; nt++) {
                mx0 = fmaxf(mx0, fmaxf(sc[mt][nt][0], sc[mt][nt][1]));
                mx1 = fmaxf(mx1, fmaxf(sc[mt][nt][2], sc[mt][nt][3]));
            }
            #pragma unroll
            for (int msk = 1; msk <= 2; msk <<= 1) {
                mx0 = fmaxf(mx0, __shfl_xor_sync(0xffffffffu, mx0, msk));
                mx1 = fmaxf(mx1, __shfl_xor_sync(0xffffffffu, mx1, msk));
            }
            float mn0 = fmaxf(mM[mt][0], mx0), mn1 = fmaxf(mM[mt][1], mx1);
            float a0 = __expf(mM[mt][0] - mn0), a1 = __expf(mM[mt][1] - mn1);
            mM[mt][0] = mn0; mM[mt][1] = mn1;

            float sum0 = 0.f, sum1 = 0.f;
            #pragma unroll
            for (int nt = 0; nt < 8; nt++) {
                sc[mt][nt][0] = __expf(sc[mt][nt][0] - mn0);
                sc[mt][nt][1] = __expf(sc[mt][nt][1] - mn0);
                sc[mt][nt][2] = __expf(sc[mt][nt][2] - mn1);
                sc[mt][nt][3] = __expf(sc[mt][nt][3] - mn1);
                sum0 += sc[mt][nt][0] + sc[mt][nt][1];
                sum1 += sc[mt][nt][2] + sc[mt][nt][3];
            }
            #pragma unroll
            for (int msk = 1; msk <= 2; msk <<= 1) {
                sum0 += __shfl_xor_sync(0xffffffffu, sum0, msk);
                sum1 += __shfl_xor_sync(0xffffffffu, sum1, msk);
            }
            lL[mt][0] = lL[mt][0]*a0 + sum0;
            lL[mt][1] = lL[mt][1]*a1 + sum1;

            #pragma unroll
            for (int nt = 0; nt < 10; nt++) {
                O[mt][nt][0] *= a0; O[mt][nt][1] *= a0;
                O[mt][nt][2] *= a1; O[mt][nt][3] *= a1;
            }

            #pragma unroll
            for (int nt = 0; nt < 8; nt++) {
                sP[(mt*16 + g    )*PPW + nt*8 + pc0] = f2tf32(sc[mt][nt][0]);
                sP[(mt*16 + g    )*PPW + nt*8 + pc1] = f2tf32(sc[mt][nt][1]);
                sP[(mt*16 + g + 8)*PPW + nt*8 + pc0] = f2tf32(sc[mt][nt][2]);
                sP[(mt*16 + g + 8)*PPW + nt*8 + pc1] = f2tf32(sc[mt][nt][3]);
            }
        }
        __syncwarp();

        if (tt + 1 < SS/64) cp_wait<1>();
        else                cp_wait<0>();
        __syncthreads();
        if (tt + 1 < SS/64)
            issueV(Vb, sm + A_OFF_V + ((tt+1)&1)*64*VP, (tt+1)*64, tid);

        #pragma unroll
        for (int ks = 0; ks < 8; ks++) {
            unsigned pa[2][4];
            #pragma unroll
            for (int mt = 0; mt < 2; mt++) {
                float2 plo = *(const float2*)&sP[(mt*16 + g    )*PPW + ks*8 + 2*t];
                float2 phi = *(const float2*)&sP[(mt*16 + g + 8)*PPW + ks*8 + 2*t];
                pa[mt][0] = __float_as_uint(plo.x);
                pa[mt][2] = __float_as_uint(plo.y);
                pa[mt][1] = __float_as_uint(phi.x);
                pa[mt][3] = __float_as_uint(phi.y);
            }
            #pragma unroll
            for (int nt = 0; nt < 10; nt++) {
                unsigned bb[2];
                bb[0] = __float_as_uint(sV[(ks*8 + t    )*VP + nt*8 + g]);
                bb[1] = __float_as_uint(sV[(ks*8 + t + 4)*VP + nt*8 + g]);
                mma_tf32(O[0][nt], pa[0], bb);
                mma_tf32(O[1][nt], pa[1], bb);
            }
        }
    }

    // ---- epilogue: normalize + tf32-round + perm8 store ----
    #pragma unroll
    for (int mt = 0; mt < 2; mt++) {
        float inv0 = 1.f / lL[mt][0], inv1 = 1.f / lL[mt][1];
        int s0r = q0 + wr + mt*16 + g, s1r = s0r + 8;
        #pragma unroll
        for (int nt = 0; nt < 10; nt++) {
            int base_c = h*DK + nt*8;
            float* row0 = g_att + ((size_t)b*SS + s0r)*DM + base_c;
            float* row1 = g_att + ((size_t)b*SS + s1r)*DM + base_c;
            row0[pc0] = f2tf32(O[mt][nt][0]*inv0);
            row0[pc1] = f2tf32(O[mt][nt][1]*inv0);
            row1[pc0] = f2tf32(O[mt][nt][2]*inv1);
            row1[pc1] = f2tf32(O[mt][nt][3]*inv1);
        }
    }
}

// ============================================================
// Kernel 3: out = A @ Wo^T + bo, single-pass tf32
// operands pre-rounded (rna) + perm8-permuted in gmem.
// 128x128 tiles, k-chunks of 32, double-buffered cp.async.
// ============================================================
#define GSF 36
#define GAB (128*GSF)
#define GEMM_SMEM_FLOATS (4*GAB)      // {A,B} x 2 buffers = 73.7 KB

__device__ __forceinline__ void gemm_issue(float* gsm, int m0, int n0, int kc, int tid)
{
    const int buf = kc & 1;
    float* sA = gsm + buf*GAB;
    float* sB = gsm + 2*GAB + buf*GAB;
    #pragma unroll
    for (int p = 0; p < 4; p++) {
        int idx = tid + p*256;
        int r = idx >> 3, seg = idx & 7;
        cp16(smem_u32(sA + r*GSF + seg*4), g_att + (size_t)(m0 + r)*DM + kc*32 + seg*4);
        cp16(smem_u32(sB + r*GSF + seg*4), g_wo  + (size_t)(n0 + r)*DM + kc*32 + seg*4);
    }
    cp_commit();
}

__global__ __launch_bounds__(256, 2) void out_gemm(
    const float* __restrict__ bo, float* __restrict__ out)
{
    extern __shared__ float gsm[];

    const int m0 = blockIdx.y * 128, n0 = blockIdx.x * 128;
    const int tid = threadIdx.x;
    const int warp = tid >> 5, lane = tid & 31;
    const int g = lane >> 2, t = lane & 3;
    const int wm = warp >> 2, wn = warp & 3;   // 2 x 4 warps, 64x32 tiles

    float acc[4][4][4];
    #pragma unroll
    for (int mt = 0; mt < 4; mt++)
        #pragma unroll
        for (int nt = 0; nt < 4; nt++)
            #pragma unroll
            for (int j = 0; j < 4; j++) acc[mt][nt][j] = 0.f;

    gemm_issue(gsm, m0, n0, 0, tid);
    gemm_issue(gsm, m0, n0, 1, tid);

    for (int kc = 0; kc < DM/32; kc++) {
        if (kc + 1 < DM/32) cp_wait<1>();
        else                cp_wait<0>();
        __syncthreads();

        const float* sA = gsm + (kc & 1)*GAB;
        const float* sB = gsm + 2*GAB + (kc & 1)*GAB;

        #pragma unroll
        for (int kk = 0; kk < 4; kk++) {
            unsigned fb[4][2];
            #pragma unroll
            for (int nt = 0; nt < 4; nt++) {
                int br = wn*32 + nt*8 + g;
                float2 bv = *(const float2*)&sB[br*GSF + kk*8 + 2*t];
                fb[nt][0] = __float_as_uint(bv.x);
                fb[nt][1] = __float_as_uint(bv.y);
            }
            #pragma unroll
            for (int mt = 0; mt < 4; mt++) {
                int mr = wm*64 + mt*16 + g;
                float2 alo = *(const float2*)&sA[ mr     *GSF + kk*8 + 2*t];
                float2 ahi = *(const float2*)&sA[(mr + 8)*GSF + kk*8 + 2*t];
                unsigned fa[4] = {__float_as_uint(alo.x), __float_as_uint(ahi.x),
                                  __float_as_uint(alo.y), __float_as_uint(ahi.y)};
                #pragma unroll
                for (int nt = 0; nt < 4; nt++)
                    mma_tf32(acc[mt][nt], fa, fb[nt]);
            }
        }
        __syncthreads();
        if (kc + 2 < DM/32)
            gemm_issue(gsm, m0, n0, kc + 2, tid);
    }

    #pragma unroll
    for (int mt = 0; mt < 4; mt++) {
        int r0 = m0 + wm*64 + mt*16 + g;
        #pragma unroll
        for (int nt = 0; nt < 4; nt++) {
            int c0 = n0 + wn*32 + nt*8 + 2*t;
            float2 b2 = *(const float2*)&bo[c0];
            float2 v0 = make_float2(acc[mt][nt][0] + b2.x, acc[mt][nt][1] + b2.y);
            float2 v1 = make_float2(acc[mt][nt][2] + b2.x, acc[mt][nt][3] + b2.y);
            *(float2*)&out[(size_t)r0*DM + c0] = v0;
            *(float2*)&out[(size_t)(r0 + 8)*DM + c0] = v1;
        }
    }
}

// ============================================================
extern "C" void kernel_launch(void* const* d_in, const int* in_sizes, int n_in,
                              void* d_out, int out_size)
{
    const float* src = (const float*)d_in[0];
    const float* Wq = (const float*)d_in[3];
    const float* bq = (const float*)d_in[4];
    const float* Wk = (const float*)d_in[5];
    const float* bk = (const float*)d_in[6];
    const float* Wv = (const float*)d_in[7];
    const float* bv = (const float*)d_in[8];
    const float* Wo = (const float*)d_in[9];
    const float* bo = (const float*)d_in[10];
    float* out = (float*)d_out;

    const int smem_qkv  = QKV_SMEM_FLOATS * (int)sizeof(float);
    const int smem_attn = ATTN_SMEM_FLOATS * (int)sizeof(float);
    const int smem_gemm = GEMM_SMEM_FLOATS * (int)sizeof(float);
    cudaFuncSetAttribute(qkv_kernel, cudaFuncAttributeMaxDynamicSharedMemorySize, smem_qkv);
    cudaFuncSetAttribute(attn_kernel, cudaFuncAttributeMaxDynamicSharedMemorySize, smem_attn);
    cudaFuncSetAttribute(out_gemm, cudaFuncAttributeMaxDynamicSharedMemorySize, smem_gemm);

    wo_round_kernel<<<(DM*(DM/4) + 255)/256, 256>>>(Wo);
    qkv_kernel<<<dim3(SS/128, NH, BB), 256, smem_qkv>>>(src, Wq, bq, Wk, bk, Wv, bv);
    attn_kernel<<<dim3(SS/256, NH, BB), 256, smem_attn>>>();
    out_gemm<<<dim3(DM/128, (BB*SS)/128), 256, smem_gemm>>>(bo, out);
}

// round 11
// speedup vs baseline: 1.6332x; 1.0885x over previous
#include <cuda_runtime.h>
#include <math.h>

#define BB 4
#define SS 1024
#define DM 1280
#define NH 16
#define DK 80
#define GR 5
#define CPG 256

// ---- scratch (device globals; no allocations allowed) ----
__device__ float g_q[(size_t)BB*NH*SS*DK];
__device__ float g_k[(size_t)BB*NH*SS*DK];
__device__ float g_v[(size_t)BB*NH*SS*DK];
__device__ float g_att[(size_t)BB*SS*DM];   // tf32-rounded, perm8 cols
__device__ float g_wo[(size_t)DM*DM];       // tf32-rounded, perm8 cols

// ---- helpers ----
__device__ __forceinline__ float f2tf32(float x) {
    unsigned u;
    asm("cvt.rna.tf32.f32 %0, %1;" : "=r"(u) : "f"(x));
    return __uint_as_float(u);
}
__device__ __forceinline__ void mma_tf32(float d[4], const unsigned a[4], const unsigned b[2]) {
    asm volatile(
        "mma.sync.aligned.m16n8k8.row.col.f32.tf32.tf32.f32 "
        "{%0,%1,%2,%3}, {%4,%5,%6,%7}, {%8,%9}, {%0,%1,%2,%3};\n"
        : "+f"(d[0]), "+f"(d[1]), "+f"(d[2]), "+f"(d[3])
        : "r"(a[0]), "r"(a[1]), "r"(a[2]), "r"(a[3]), "r"(b[0]), "r"(b[1]));
}
__device__ __forceinline__ unsigned smem_u32(const void* p) {
    return (unsigned)__cvta_generic_to_shared(p);
}
__device__ __forceinline__ void cp16(unsigned s, const void* g) {
    asm volatile("cp.async.cg.shared.global [%0], [%1], 16;" :: "r"(s), "l"(g));
}
__device__ __forceinline__ void cp_commit() { asm volatile("cp.async.commit_group;"); }
template<int N> __device__ __forceinline__ void cp_wait() {
    asm volatile("cp.async.wait_group %0;" :: "n"(N));
}
// column pairing within 8-group: (t, t+4) -> adjacent (2t, 2t+1)
__device__ __forceinline__ int perm8(int c) {
    return (c & ~7) | ((c & 3) << 1) | ((c >> 2) & 1);
}

// ============================================================
// Kernel 0: round Wo to tf32 and store with perm8 column layout
// ============================================================
__global__ __launch_bounds__(256) void wo_round_kernel(const float* __restrict__ Wo)
{
    int i = blockIdx.x * 256 + threadIdx.x;    // over DM*DM/4 float4s
    if (i >= DM * (DM/4)) return;
    int n = i / (DM/4), k4 = (i % (DM/4)) * 4;
    float4 v = *(const float4*)&Wo[(size_t)n*DM + k4];
    int blk = k4 & ~7, off = k4 & 7;           // off = 0 or 4
    float* dst = g_wo + (size_t)n*DM + blk;
    dst[perm8(off    )] = f2tf32(v.x);
    dst[perm8(off + 1)] = f2tf32(v.y);
    dst[perm8(off + 2)] = f2tf32(v.z);
    dst[perm8(off + 3)] = f2tf32(v.w);
}

// ============================================================
// Kernel 1: channel shuffle + per-head QKV projections
// (unchanged; 1/sqrt(dk) folded into Wq/bq; linear outputs)
// ============================================================
#define XS 84
#define QKV_SMEM_FLOATS (128*XS + 80*XS + 80)

__global__ __launch_bounds__(256) void qkv_kernel(
    const float* __restrict__ src,
    const float* __restrict__ Wq, const float* __restrict__ bq,
    const float* __restrict__ Wk, const float* __restrict__ bk,
    const float* __restrict__ Wv, const float* __restrict__ bv)
{
    extern __shared__ float qsm[];
    float* sX = qsm;              // [128][84]
    float* sW = sX + 128*XS;      // [80][84]
    float* sb = sW + 80*XS;       // [80]

    const int b = blockIdx.z, h = blockIdx.y, s0 = blockIdx.x * 128;
    const int tid = threadIdx.x;
    const int warp = tid >> 5, lane = tid & 31;
    const int g = lane >> 2, t = lane & 3;
    const int wr = warp * 16;

    #pragma unroll
    for (int p = 0; p < 10; p++) {
        int idx = tid + p*256;
        int r = idx / 20, q = idx % 20;
        int j = q / 4, m = q % 4;
        float4 v = *(const float4*)&src[((size_t)b*SS + s0 + r)*DM + j*CPG + 16*h + m*4];
        int kbase = (m*4)*5 + j;
        sX[r*XS + kbase     ] = f2tf32(v.x);
        sX[r*XS + kbase + 5 ] = f2tf32(v.y);
        sX[r*XS + kbase + 10] = f2tf32(v.z);
        sX[r*XS + kbase + 15] = f2tf32(v.w);
    }
    __syncthreads();

    unsigned qa[10][4];
    #pragma unroll
    for (int ks = 0; ks < 10; ks++) {
        qa[ks][0] = __float_as_uint(sX[(wr + g    )*XS + ks*8 + t    ]);
        qa[ks][1] = __float_as_uint(sX[(wr + g + 8)*XS + ks*8 + t    ]);
        qa[ks][2] = __float_as_uint(sX[(wr + g    )*XS + ks*8 + t + 4]);
        qa[ks][3] = __float_as_uint(sX[(wr + g + 8)*XS + ks*8 + t + 4]);
    }

    const float* Ws[3] = {Wq, Wk, Wv};
    const float* bs[3] = {bq, bk, bv};
    float* outs[3] = {g_q, g_k, g_v};
    const float scl = rsqrtf((float)DK);

    for (int pj = 0; pj < 3; pj++) {
        const float s = (pj == 0) ? scl : 1.f;
        __syncthreads();
        for (int i = tid; i < 1600; i += 256) {
            int e = i / 20, k = (i % 20) * 4;
            float4 w = *(const float4*)&Ws[pj][h*DK*DK + e*DK + k];
            float4 wr4 = make_float4(f2tf32(w.x*s), f2tf32(w.y*s), f2tf32(w.z*s), f2tf32(w.w*s));
            *(float4*)&sW[e*XS + k] = wr4;
        }
        if (tid < DK) sb[tid] = bs[pj][h*DK + tid] * s;
        __syncthreads();

        float acc[10][4];
        #pragma unroll
        for (int nt = 0; nt < 10; nt++)
            #pragma unroll
            for (int j = 0; j < 4; j++) acc[nt][j] = 0.f;

        #pragma unroll
        for (int ks = 0; ks < 10; ks++) {
            #pragma unroll
            for (int nt = 0; nt < 10; nt++) {
                unsigned bb[2];
                bb[0] = __float_as_uint(sW[(nt*8 + g)*XS + ks*8 + t    ]);
                bb[1] = __float_as_uint(sW[(nt*8 + g)*XS + ks*8 + t + 4]);
                mma_tf32(acc[nt], qa[ks], bb);
            }
        }

        float* outp = outs[pj] + (((size_t)b*NH + h)*SS + s0) * DK;
        #pragma unroll
        for (int nt = 0; nt < 10; nt++) {
            int c = nt*8 + 2*t;
            float b0 = sb[c], b1 = sb[c + 1];
            float2 v0 = make_float2(f2tf32(acc[nt][0] + b0), f2tf32(acc[nt][1] + b1));
            float2 v1 = make_float2(f2tf32(acc[nt][2] + b0), f2tf32(acc[nt][3] + b1));
            *(float2*)&outp[(size_t)(wr + g    )*DK + c] = v0;
            *(float2*)&outp[(size_t)(wr + g + 8)*DK + c] = v1;
        }
    }
}

// ============================================================
// Kernel 2: flash attention, tf32 mma
// 256-row q tiles, 8 warps x 32 rows; conflict-free strides:
// QP=84 (paired Q loads), KP=84 (scalar K loads), VP=88, PPW=68
// ============================================================
#define QP 84
#define KP 84
#define VP 88
#define PPW 68
#define A_OFF_Q 0
#define A_OFF_K (256*QP)
#define A_OFF_V (A_OFF_K + 64*KP)
#define A_OFF_P (A_OFF_V + 2*64*VP)
#define ATTN_SMEM_FLOATS (A_OFF_P + 8*32*PPW)    // 55552 fl = 222 KB

__device__ __forceinline__ void issueK(const float* Kb, float* sK, int kt, int tid)
{
    #pragma unroll
    for (int p = 0; p < 5; p++) {
        int c = tid + p*256;
        int r = c / 20, seg = c % 20;
        cp16(smem_u32(sK + r*KP + seg*4), Kb + (size_t)(kt + r)*DK + seg*4);
    }
    cp_commit();
}
__device__ __forceinline__ void issueV(const float* Vb, float* sV, int kt, int tid)
{
    #pragma unroll
    for (int p = 0; p < 5; p++) {
        int c = tid + p*256;
        int r = c / 20, seg = c % 20;
        cp16(smem_u32(sV + r*VP + seg*4), Vb + (size_t)(kt + r)*DK + seg*4);
    }
    cp_commit();
}

__global__ __launch_bounds__(256) void attn_kernel()
{
    extern __shared__ float sm[];
    float* sQ = sm + A_OFF_Q;
    float* sK = sm + A_OFF_K;

    const int b = blockIdx.z, h = blockIdx.y, q0 = blockIdx.x * 256;
    const int tid = threadIdx.x;
    const int warp = tid >> 5, lane = tid & 31;
    const int g = lane >> 2, t = lane & 3;
    const int wr = warp * 32;
    float* sP = sm + A_OFF_P + warp * 32 * PPW;   // warp-private

    const size_t base = ((size_t)b*NH + h) * SS * DK;
    const float* Qb = g_q + base;     // pre-scaled, tf32-rounded
    const float* Kb = g_k + base;
    const float* Vb = g_v + base;

    // stage Q (column-paired): 5120 float4 pieces
    #pragma unroll
    for (int p = 0; p < 20; p++) {
        int idx = tid + p*256;
        int r = idx / 20, q4 = idx % 20;
        float4 v = *(const float4*)&Qb[(size_t)(q0 + r)*DK + q4*4];
        int k = q4*4;
        sQ[r*QP + perm8(k    )] = v.x;
        sQ[r*QP + perm8(k + 1)] = v.y;
        sQ[r*QP + perm8(k + 2)] = v.z;
        sQ[r*QP + perm8(k + 3)] = v.w;
    }
    issueK(Kb, sK, 0, tid);                       // group K0
    issueV(Vb, sm + A_OFF_V, 0, tid);             // group V0

    float O[2][10][4];
    #pragma unroll
    for (int mt = 0; mt < 2; mt++)
        #pragma unroll
        for (int nt = 0; nt < 10; nt++)
            #pragma unroll
            for (int j = 0; j < 4; j++) O[mt][nt][j] = 0.f;
    float mM[2][2], lL[2][2];
    #pragma unroll
    for (int mt = 0; mt < 2; mt++) {
        mM[mt][0] = mM[mt][1] = -1e30f;
        lL[mt][0] = lL[mt][1] = 0.f;
    }

    const int pc0 = ((2*t & 3) << 1) | ((2*t) >> 2);
    const int pc1 = (((2*t+1) & 3) << 1) | ((2*t+1) >> 2);

    for (int tt = 0; tt < SS/64; tt++) {
        float* sV = sm + A_OFF_V + (tt & 1) * 64*VP;

        cp_wait<1>();        // K(tt) done (V(tt) may be pending)
        __syncthreads();

        float sc[2][8][4];
        #pragma unroll
        for (int mt = 0; mt < 2; mt++)
            #pragma unroll
            for (int nt = 0; nt < 8; nt++)
                #pragma unroll
                for (int j = 0; j < 4; j++) sc[mt][nt][j] = 0.f;

        #pragma unroll
        for (int ks = 0; ks < 10; ks++) {
            unsigned qa2[2][4];
            #pragma unroll
            for (int mt = 0; mt < 2; mt++) {
                float2 qlo = *(const float2*)&sQ[(wr + mt*16 + g    )*QP + ks*8 + 2*t];
                float2 qhi = *(const float2*)&sQ[(wr + mt*16 + g + 8)*QP + ks*8 + 2*t];
                qa2[mt][0] = __float_as_uint(qlo.x);
                qa2[mt][2] = __float_as_uint(qlo.y);
                qa2[mt][1] = __float_as_uint(qhi.x);
                qa2[mt][3] = __float_as_uint(qhi.y);
            }
            #pragma unroll
            for (int nt = 0; nt < 8; nt++) {
                unsigned bb[2];
                bb[0] = __float_as_uint(sK[(nt*8 + g)*KP + ks*8 + t    ]);
                bb[1] = __float_as_uint(sK[(nt*8 + g)*KP + ks*8 + t + 4]);
                mma_tf32(sc[0][nt], qa2[0], bb);
                mma_tf32(sc[1][nt], qa2[1], bb);
            }
        }
        __syncthreads();
        if (tt + 1 < SS/64)
            issueK(Kb, sK, (tt+1)*64, tid);

        #pragma unroll
        for (int mt = 0; mt < 2; mt++) {
            float mx0 = -1e30f, mx1 = -1e30f;
            #pragma unroll
            for (int nt = 0; nt < 8; nt++) {
                mx0 = fmaxf(mx0, fmaxf(sc[mt][nt][0], sc[mt][nt][1]));
                mx1 = fmaxf(mx1, fmaxf(sc[mt][nt][2], sc[mt][nt][3]));
            }
            #pragma unroll
            for (int msk = 1; msk <= 2; msk <<= 1) {
                mx0 = fmaxf(mx0, __shfl_xor_sync(0xffffffffu, mx0, msk));
                mx1 = fmaxf(mx1, __shfl_xor_sync(0xffffffffu, mx1, msk));
            }
            float mn0 = fmaxf(mM[mt][0], mx0), mn1 = fmaxf(mM[mt][1], mx1);
            float a0 = __expf(mM[mt][0] - mn0), a1 = __expf(mM[mt][1] - mn1);
            mM[mt][0] = mn0; mM[mt][1] = mn1;

            float sum0 = 0.f, sum1 = 0.f;
            #pragma unroll
            for (int nt = 0; nt < 8; nt++) {
                sc[mt][nt][0] = __expf(sc[mt][nt][0] - mn0);
                sc[mt][nt][1] = __expf(sc[mt][nt][1] - mn0);
                sc[mt][nt][2] = __expf(sc[mt][nt][2] - mn1);
                sc[mt][nt][3] = __expf(sc[mt][nt][3] - mn1);
                sum0 += sc[mt][nt][0] + sc[mt][nt][1];
                sum1 += sc[mt][nt][2] + sc[mt][nt][3];
            }
            #pragma unroll
            for (int msk = 1; msk <= 2; msk <<= 1) {
                sum0 += __shfl_xor_sync(0xffffffffu, sum0, msk);
                sum1 += __shfl_xor_sync(0xffffffffu, sum1, msk);
            }
            lL[mt][0] = lL[mt][0]*a0 + sum0;
            lL[mt][1] = lL[mt][1]*a1 + sum1;

            #pragma unroll
            for (int nt = 0; nt < 10; nt++) {
                O[mt][nt][0] *= a0; O[mt][nt][1] *= a0;
                O[mt][nt][2] *= a1; O[mt][nt][3] *= a1;
            }

            #pragma unroll
            for (int nt = 0; nt < 8; nt++) {
                sP[(mt*16 + g    )*PPW + nt*8 + pc0] = f2tf32(sc[mt][nt][0]);
                sP[(mt*16 + g    )*PPW + nt*8 + pc1] = f2tf32(sc[mt][nt][1]);
                sP[(mt*16 + g + 8)*PPW + nt*8 + pc0] = f2tf32(sc[mt][nt][2]);
                sP[(mt*16 + g + 8)*PPW + nt*8 + pc1] = f2tf32(sc[mt][nt][3]);
            }
        }
        __syncwarp();

        if (tt + 1 < SS/64) cp_wait<1>();
        else                cp_wait<0>();
        __syncthreads();
        if (tt + 1 < SS/64)
            issueV(Vb, sm + A_OFF_V + ((tt+1)&1)*64*VP, (tt+1)*64, tid);

        #pragma unroll
        for (int ks = 0; ks < 8; ks++) {
            unsigned pa[2][4];
            #pragma unroll
            for (int mt = 0; mt < 2; mt++) {
                float2 plo = *(const float2*)&sP[(mt*16 + g    )*PPW + ks*8 + 2*t];
                float2 phi = *(const float2*)&sP[(mt*16 + g + 8)*PPW + ks*8 + 2*t];
                pa[mt][0] = __float_as_uint(plo.x);
                pa[mt][2] = __float_as_uint(plo.y);
                pa[mt][1] = __float_as_uint(phi.x);
                pa[mt][3] = __float_as_uint(phi.y);
            }
            #pragma unroll
            for (int nt = 0; nt < 10; nt++) {
                unsigned bb[2];
                bb[0] = __float_as_uint(sV[(ks*8 + t    )*VP + nt*8 + g]);
                bb[1] = __float_as_uint(sV[(ks*8 + t + 4)*VP + nt*8 + g]);
                mma_tf32(O[0][nt], pa[0], bb);
                mma_tf32(O[1][nt], pa[1], bb);
            }
        }
    }

    // ---- epilogue: normalize + tf32-round + perm8 store ----
    #pragma unroll
    for (int mt = 0; mt < 2; mt++) {
        float inv0 = 1.f / lL[mt][0], inv1 = 1.f / lL[mt][1];
        int s0r = q0 + wr + mt*16 + g, s1r = s0r + 8;
        #pragma unroll
        for (int nt = 0; nt < 10; nt++) {
            int base_c = h*DK + nt*8;
            float* row0 = g_att + ((size_t)b*SS + s0r)*DM + base_c;
            float* row1 = g_att + ((size_t)b*SS + s1r)*DM + base_c;
            row0[pc0] = f2tf32(O[mt][nt][0]*inv0);
            row0[pc1] = f2tf32(O[mt][nt][1]*inv0);
            row1[pc0] = f2tf32(O[mt][nt][2]*inv1);
            row1[pc1] = f2tf32(O[mt][nt][3]*inv1);
        }
    }
}

// ============================================================
// Kernel 3: out = A @ Wo^T + bo, single-pass tf32
// 128x160 tiles -> 256 CTAs = ONE full wave at occ 2.
// 8 warps (2x4), warp tile 64x40 (4 m-tiles x 5 n-tiles).
// ============================================================
#define GSF 36
#define GA1 (128*GSF)
#define GB1 (160*GSF)
#define GEMM_SMEM_FLOATS (2*GA1 + 2*GB1)   // 82.9 KB

__device__ __forceinline__ void gemm_issue(float* gsm, int m0, int n0, int kc, int tid)
{
    const int buf = kc & 1;
    float* sA = gsm + buf*GA1;
    float* sB = gsm + 2*GA1 + buf*GB1;
    #pragma unroll
    for (int p = 0; p < 4; p++) {          // A: 128 rows x 8 segs = 1024
        int idx = tid + p*256;
        int r = idx >> 3, seg = idx & 7;
        cp16(smem_u32(sA + r*GSF + seg*4), g_att + (size_t)(m0 + r)*DM + kc*32 + seg*4);
    }
    #pragma unroll
    for (int p = 0; p < 5; p++) {          // B: 160 rows x 8 segs = 1280
        int idx = tid + p*256;
        int r = idx >> 3, seg = idx & 7;
        cp16(smem_u32(sB + r*GSF + seg*4), g_wo + (size_t)(n0 + r)*DM + kc*32 + seg*4);
    }
    cp_commit();
}

__global__ __launch_bounds__(256, 2) void out_gemm(
    const float* __restrict__ bo, float* __restrict__ out)
{
    extern __shared__ float gsm[];

    const int m0 = blockIdx.y * 128, n0 = blockIdx.x * 160;
    const int tid = threadIdx.x;
    const int warp = tid >> 5, lane = tid & 31;
    const int g = lane >> 2, t = lane & 3;
    const int wm = warp >> 2, wn = warp & 3;   // 2 x 4 warps, 64x40 tiles

    float acc[4][5][4];
    #pragma unroll
    for (int mt = 0; mt < 4; mt++)
        #pragma unroll
        for (int nt = 0; nt < 5; nt++)
            #pragma unroll
            for (int j = 0; j < 4; j++) acc[mt][nt][j] = 0.f;

    gemm_issue(gsm, m0, n0, 0, tid);
    gemm_issue(gsm, m0, n0, 1, tid);

    for (int kc = 0; kc < DM/32; kc++) {
        if (kc + 1 < DM/32) cp_wait<1>();
        else                cp_wait<0>();
        __syncthreads();

        const float* sA = gsm + (kc & 1)*GA1;
        const float* sB = gsm + 2*GA1 + (kc & 1)*GB1;

        #pragma unroll
        for (int kk = 0; kk < 4; kk++) {
            unsigned fb[5][2];
            #pragma unroll
            for (int nt = 0; nt < 5; nt++) {
                int br = wn*40 + nt*8 + g;
                float2 bv = *(const float2*)&sB[br*GSF + kk*8 + 2*t];
                fb[nt][0] = __float_as_uint(bv.x);
                fb[nt][1] = __float_as_uint(bv.y);
            }
            #pragma unroll
            for (int mt = 0; mt < 4; mt++) {
                int mr = wm*64 + mt*16 + g;
                float2 alo = *(const float2*)&sA[ mr     *GSF + kk*8 + 2*t];
                float2 ahi = *(const float2*)&sA[(mr + 8)*GSF + kk*8 + 2*t];
                unsigned fa[4] = {__float_as_uint(alo.x), __float_as_uint(ahi.x),
                                  __float_as_uint(alo.y), __float_as_uint(ahi.y)};
                #pragma unroll
                for (int nt = 0; nt < 5; nt++)
                    mma_tf32(acc[mt][nt], fa, fb[nt]);
            }
        }
        __syncthreads();
        if (kc + 2 < DM/32)
            gemm_issue(gsm, m0, n0, kc + 2, tid);
    }

    #pragma unroll
    for (int mt = 0; mt < 4; mt++) {
        int r0 = m0 + wm*64 + mt*16 + g;
        #pragma unroll
        for (int nt = 0; nt < 5; nt++) {
            int c0 = n0 + wn*40 + nt*8 + 2*t;
            float2 b2 = *(const float2*)&bo[c0];
            float2 v0 = make_float2(acc[mt][nt][0] + b2.x, acc[mt][nt][1] + b2.y);
            float2 v1 = make_float2(acc[mt][nt][2] + b2.x, acc[mt][nt][3] + b2.y);
            *(float2*)&out[(size_t)r0*DM + c0] = v0;
            *(float2*)&out[(size_t)(r0 + 8)*DM + c0] = v1;
        }
    }
}

// ============================================================
extern "C" void kernel_launch(void* const* d_in, const int* in_sizes, int n_in,
                              void* d_out, int out_size)
{
    const float* src = (const float*)d_in[0];
    const float* Wq = (const float*)d_in[3];
    const float* bq = (const float*)d_in[4];
    const float* Wk = (const float*)d_in[5];
    const float* bk = (const float*)d_in[6];
    const float* Wv = (const float*)d_in[7];
    const float* bv = (const float*)d_in[8];
    const float* Wo = (const float*)d_in[9];
    const float* bo = (const float*)d_in[10];
    float* out = (float*)d_out;

    const int smem_qkv  = QKV_SMEM_FLOATS * (int)sizeof(float);
    const int smem_attn = ATTN_SMEM_FLOATS * (int)sizeof(float);
    const int smem_gemm = GEMM_SMEM_FLOATS * (int)sizeof(float);
    cudaFuncSetAttribute(qkv_kernel, cudaFuncAttributeMaxDynamicSharedMemorySize, smem_qkv);
    cudaFuncSetAttribute(attn_kernel, cudaFuncAttributeMaxDynamicSharedMemorySize, smem_attn);
    cudaFuncSetAttribute(out_gemm, cudaFuncAttributeMaxDynamicSharedMemorySize, smem_gemm);

    wo_round_kernel<<<(DM*(DM/4) + 255)/256, 256>>>(Wo);
    qkv_kernel<<<dim3(SS/128, NH, BB), 256, smem_qkv>>>(src, Wq, bq, Wk, bk, Wv, bv);
    attn_kernel<<<dim3(SS/256, NH, BB), 256, smem_attn>>>();
    out_gemm<<<dim3(DM/160, (BB*SS)/128), 256, smem_gemm>>>(bo, out);
}

// round 12
// speedup vs baseline: 1.6414x; 1.0050x over previous
#include <cuda_runtime.h>
#include <math.h>

#define BB 4
#define SS 1024
#define DM 1280
#define NH 16
#define DK 80
#define GR 5
#define CPG 256

// ---- scratch (device globals; no allocations allowed) ----
__device__ float g_q[(size_t)BB*NH*SS*DK];
__device__ float g_k[(size_t)BB*NH*SS*DK];
__device__ float g_v[(size_t)BB*NH*SS*DK];
__device__ float g_att[(size_t)BB*SS*DM];   // tf32-rounded, perm8 cols
__device__ float g_wo[(size_t)DM*DM];       // tf32-rounded, perm8 cols

// ---- helpers ----
__device__ __forceinline__ float f2tf32(float x) {
    unsigned u;
    asm("cvt.rna.tf32.f32 %0, %1;" : "=r"(u) : "f"(x));
    return __uint_as_float(u);
}
__device__ __forceinline__ void mma_tf32(float d[4], const unsigned a[4], const unsigned b[2]) {
    asm volatile(
        "mma.sync.aligned.m16n8k8.row.col.f32.tf32.tf32.f32 "
        "{%0,%1,%2,%3}, {%4,%5,%6,%7}, {%8,%9}, {%0,%1,%2,%3};\n"
        : "+f"(d[0]), "+f"(d[1]), "+f"(d[2]), "+f"(d[3])
        : "r"(a[0]), "r"(a[1]), "r"(a[2]), "r"(a[3]), "r"(b[0]), "r"(b[1]));
}
__device__ __forceinline__ unsigned smem_u32(const void* p) {
    return (unsigned)__cvta_generic_to_shared(p);
}
__device__ __forceinline__ void cp16(unsigned s, const void* g) {
    asm volatile("cp.async.cg.shared.global [%0], [%1], 16;" :: "r"(s), "l"(g));
}
__device__ __forceinline__ void cp_commit() { asm volatile("cp.async.commit_group;"); }
template<int N> __device__ __forceinline__ void cp_wait() {
    asm volatile("cp.async.wait_group %0;" :: "n"(N));
}
// column pairing within 8-group: (t, t+4) -> adjacent (2t, 2t+1)
__device__ __forceinline__ int perm8(int c) {
    return (c & ~7) | ((c & 3) << 1) | ((c >> 2) & 1);
}

// ============================================================
// Kernel 0: round Wo to tf32 and store with perm8 column layout
// ============================================================
__global__ __launch_bounds__(256) void wo_round_kernel(const float* __restrict__ Wo)
{
    int i = blockIdx.x * 256 + threadIdx.x;    // over DM*DM/4 float4s
    if (i >= DM * (DM/4)) return;
    int n = i / (DM/4), k4 = (i % (DM/4)) * 4;
    float4 v = *(const float4*)&Wo[(size_t)n*DM + k4];
    int blk = k4 & ~7, off = k4 & 7;           // off = 0 or 4
    float* dst = g_wo + (size_t)n*DM + blk;
    dst[perm8(off    )] = f2tf32(v.x);
    dst[perm8(off + 1)] = f2tf32(v.y);
    dst[perm8(off + 2)] = f2tf32(v.z);
    dst[perm8(off + 3)] = f2tf32(v.w);
}

// ============================================================
// Kernel 1: channel shuffle + per-head QKV projections
// (unchanged; 1/sqrt(dk) folded into Wq/bq; linear outputs)
// ============================================================
#define XS 84
#define QKV_SMEM_FLOATS (128*XS + 80*XS + 80)

__global__ __launch_bounds__(256) void qkv_kernel(
    const float* __restrict__ src,
    const float* __restrict__ Wq, const float* __restrict__ bq,
    const float* __restrict__ Wk, const float* __restrict__ bk,
    const float* __restrict__ Wv, const float* __restrict__ bv)
{
    extern __shared__ float qsm[];
    float* sX = qsm;              // [128][84]
    float* sW = sX + 128*XS;      // [80][84]
    float* sb = sW + 80*XS;       // [80]

    const int b = blockIdx.z, h = blockIdx.y, s0 = blockIdx.x * 128;
    const int tid = threadIdx.x;
    const int warp = tid >> 5, lane = tid & 31;
    const int g = lane >> 2, t = lane & 3;
    const int wr = warp * 16;

    #pragma unroll
    for (int p = 0; p < 10; p++) {
        int idx = tid + p*256;
        int r = idx / 20, q = idx % 20;
        int j = q / 4, m = q % 4;
        float4 v = *(const float4*)&src[((size_t)b*SS + s0 + r)*DM + j*CPG + 16*h + m*4];
        int kbase = (m*4)*5 + j;
        sX[r*XS + kbase     ] = f2tf32(v.x);
        sX[r*XS + kbase + 5 ] = f2tf32(v.y);
        sX[r*XS + kbase + 10] = f2tf32(v.z);
        sX[r*XS + kbase + 15] = f2tf32(v.w);
    }
    __syncthreads();

    unsigned qa[10][4];
    #pragma unroll
    for (int ks = 0; ks < 10; ks++) {
        qa[ks][0] = __float_as_uint(sX[(wr + g    )*XS + ks*8 + t    ]);
        qa[ks][1] = __float_as_uint(sX[(wr + g + 8)*XS + ks*8 + t    ]);
        qa[ks][2] = __float_as_uint(sX[(wr + g    )*XS + ks*8 + t + 4]);
        qa[ks][3] = __float_as_uint(sX[(wr + g + 8)*XS + ks*8 + t + 4]);
    }

    const float* Ws[3] = {Wq, Wk, Wv};
    const float* bs[3] = {bq, bk, bv};
    float* outs[3] = {g_q, g_k, g_v};
    const float scl = rsqrtf((float)DK);

    for (int pj = 0; pj < 3; pj++) {
        const float s = (pj == 0) ? scl : 1.f;
        __syncthreads();
        for (int i = tid; i < 1600; i += 256) {
            int e = i / 20, k = (i % 20) * 4;
            float4 w = *(const float4*)&Ws[pj][h*DK*DK + e*DK + k];
            float4 wr4 = make_float4(f2tf32(w.x*s), f2tf32(w.y*s), f2tf32(w.z*s), f2tf32(w.w*s));
            *(float4*)&sW[e*XS + k] = wr4;
        }
        if (tid < DK) sb[tid] = bs[pj][h*DK + tid] * s;
        __syncthreads();

        float acc[10][4];
        #pragma unroll
        for (int nt = 0; nt < 10; nt++)
            #pragma unroll
            for (int j = 0; j < 4; j++) acc[nt][j] = 0.f;

        #pragma unroll
        for (int ks = 0; ks < 10; ks++) {
            #pragma unroll
            for (int nt = 0; nt < 10; nt++) {
                unsigned bb[2];
                bb[0] = __float_as_uint(sW[(nt*8 + g)*XS + ks*8 + t    ]);
                bb[1] = __float_as_uint(sW[(nt*8 + g)*XS + ks*8 + t + 4]);
                mma_tf32(acc[nt], qa[ks], bb);
            }
        }

        float* outp = outs[pj] + (((size_t)b*NH + h)*SS + s0) * DK;
        #pragma unroll
        for (int nt = 0; nt < 10; nt++) {
            int c = nt*8 + 2*t;
            float b0 = sb[c], b1 = sb[c + 1];
            float2 v0 = make_float2(f2tf32(acc[nt][0] + b0), f2tf32(acc[nt][1] + b1));
            float2 v1 = make_float2(f2tf32(acc[nt][2] + b0), f2tf32(acc[nt][3] + b1));
            *(float2*)&outp[(size_t)(wr + g    )*DK + c] = v0;
            *(float2*)&outp[(size_t)(wr + g + 8)*DK + c] = v1;
        }
    }
}

// ============================================================
// Kernel 2: flash attention, tf32 mma — OCCUPANCY 2
// 128-row q tiles, 8 warps x 16 rows; Q cached in registers
// (staged through smem region later reused for P).
// Strides verified: QSP=88, PPW=72 (paired: ≡8/24 mod 32),
// KP=84, VP=88 (scalar: 4·odd / t-indexed OK).
// smem 111.6 KB -> 2 CTAs/SM.
// ============================================================
#define KP 84
#define VP 88
#define QSP 88
#define PPW 72
#define A_OFF_K 0
#define A_OFF_V (64*KP)
#define A_OFF_QP (A_OFF_V + 2*64*VP)
#define ATTN_SMEM_FLOATS (A_OFF_QP + 128*QSP)   // 27904 fl = 111.6 KB

__device__ __forceinline__ void issueK(const float* Kb, float* sK, int kt, int tid)
{
    #pragma unroll
    for (int p = 0; p < 5; p++) {
        int c = tid + p*256;
        int r = c / 20, seg = c % 20;
        cp16(smem_u32(sK + r*KP + seg*4), Kb + (size_t)(kt + r)*DK + seg*4);
    }
    cp_commit();
}
__device__ __forceinline__ void issueV(const float* Vb, float* sV, int kt, int tid)
{
    #pragma unroll
    for (int p = 0; p < 5; p++) {
        int c = tid + p*256;
        int r = c / 20, seg = c % 20;
        cp16(smem_u32(sV + r*VP + seg*4), Vb + (size_t)(kt + r)*DK + seg*4);
    }
    cp_commit();
}

__global__ __launch_bounds__(256, 2) void attn_kernel()
{
    extern __shared__ float sm[];
    float* sK = sm + A_OFF_K;
    float* sQs = sm + A_OFF_QP;                   // Q staging (then P)

    const int b = blockIdx.z, h = blockIdx.y, q0 = blockIdx.x * 128;
    const int tid = threadIdx.x;
    const int warp = tid >> 5, lane = tid & 31;
    const int g = lane >> 2, t = lane & 3;
    const int wr = warp * 16;
    float* sP = sm + A_OFF_QP + warp * 16 * PPW;  // warp-private (overlays Q stage)

    const size_t base = ((size_t)b*NH + h) * SS * DK;
    const float* Qb = g_q + base;     // pre-scaled, tf32-rounded
    const float* Kb = g_k + base;
    const float* Vb = g_v + base;

    issueK(Kb, sK, 0, tid);                       // group K0
    issueV(Vb, sm + A_OFF_V, 0, tid);             // group V0

    // stage Q (column-paired, stride 88): 2560 float4 pieces
    #pragma unroll
    for (int p = 0; p < 10; p++) {
        int idx = tid + p*256;
        int r = idx / 20, q4 = idx % 20;
        float4 v = *(const float4*)&Qb[(size_t)(q0 + r)*DK + q4*4];
        int k = q4*4;
        sQs[r*QSP + perm8(k    )] = v.x;
        sQs[r*QSP + perm8(k + 1)] = v.y;
        sQs[r*QSP + perm8(k + 2)] = v.z;
        sQs[r*QSP + perm8(k + 3)] = v.w;
    }
    __syncthreads();

    // cache Q A-fragments in registers (paired LDS.64, conflict-free)
    unsigned qa[10][4];
    #pragma unroll
    for (int ks = 0; ks < 10; ks++) {
        float2 qlo = *(const float2*)&sQs[(wr + g    )*QSP + ks*8 + 2*t];
        float2 qhi = *(const float2*)&sQs[(wr + g + 8)*QSP + ks*8 + 2*t];
        qa[ks][0] = __float_as_uint(qlo.x);
        qa[ks][2] = __float_as_uint(qlo.y);
        qa[ks][1] = __float_as_uint(qhi.x);
        qa[ks][3] = __float_as_uint(qhi.y);
    }
    // loop-top __syncthreads (after cp_wait) orders qa loads before P stores

    float O[10][4];
    #pragma unroll
    for (int nt = 0; nt < 10; nt++)
        #pragma unroll
        for (int j = 0; j < 4; j++) O[nt][j] = 0.f;
    float m0 = -1e30f, m1 = -1e30f, l0 = 0.f, l1 = 0.f;

    const int pc0 = ((2*t & 3) << 1) | ((2*t) >> 2);
    const int pc1 = (((2*t+1) & 3) << 1) | ((2*t+1) >> 2);

    for (int tt = 0; tt < SS/64; tt++) {
        float* sV = sm + A_OFF_V + (tt & 1) * 64*VP;

        cp_wait<1>();        // K(tt) done (V(tt) may be pending)
        __syncthreads();

        // ---- scores: 16x64, qa from regs, K scalar (conflict-free) ----
        float sc[8][4];
        #pragma unroll
        for (int nt = 0; nt < 8; nt++)
            #pragma unroll
            for (int j = 0; j < 4; j++) sc[nt][j] = 0.f;

        #pragma unroll
        for (int ks = 0; ks < 10; ks++) {
            #pragma unroll
            for (int nt = 0; nt < 8; nt++) {
                unsigned bb[2];
                bb[0] = __float_as_uint(sK[(nt*8 + g)*KP + ks*8 + t    ]);
                bb[1] = __float_as_uint(sK[(nt*8 + g)*KP + ks*8 + t + 4]);
                mma_tf32(sc[nt], qa[ks], bb);
            }
        }
        __syncthreads();     // all warps done with sK
        if (tt + 1 < SS/64)
            issueK(Kb, sK, (tt+1)*64, tid);

        // ---- online softmax ----
        float mx0 = -1e30f, mx1 = -1e30f;
        #pragma unroll
        for (int nt = 0; nt < 8; nt++) {
            mx0 = fmaxf(mx0, fmaxf(sc[nt][0], sc[nt][1]));
            mx1 = fmaxf(mx1, fmaxf(sc[nt][2], sc[nt][3]));
        }
        #pragma unroll
        for (int msk = 1; msk <= 2; msk <<= 1) {
            mx0 = fmaxf(mx0, __shfl_xor_sync(0xffffffffu, mx0, msk));
            mx1 = fmaxf(mx1, __shfl_xor_sync(0xffffffffu, mx1, msk));
        }
        float mn0 = fmaxf(m0, mx0), mn1 = fmaxf(m1, mx1);
        float a0 = __expf(m0 - mn0), a1 = __expf(m1 - mn1);
        m0 = mn0; m1 = mn1;

        float sum0 = 0.f, sum1 = 0.f;
        #pragma unroll
        for (int nt = 0; nt < 8; nt++) {
            sc[nt][0] = __expf(sc[nt][0] - m0);
            sc[nt][1] = __expf(sc[nt][1] - m0);
            sc[nt][2] = __expf(sc[nt][2] - m1);
            sc[nt][3] = __expf(sc[nt][3] - m1);
            sum0 += sc[nt][0] + sc[nt][1];
            sum1 += sc[nt][2] + sc[nt][3];
        }
        #pragma unroll
        for (int msk = 1; msk <= 2; msk <<= 1) {
            sum0 += __shfl_xor_sync(0xffffffffu, sum0, msk);
            sum1 += __shfl_xor_sync(0xffffffffu, sum1, msk);
        }
        l0 = l0*a0 + sum0;
        l1 = l1*a1 + sum1;

        #pragma unroll
        for (int nt = 0; nt < 10; nt++) {
            O[nt][0] *= a0; O[nt][1] *= a0;
            O[nt][2] *= a1; O[nt][3] *= a1;
        }

        // ---- stage P (warp-private, stride 72, paired cols) ----
        #pragma unroll
        for (int nt = 0; nt < 8; nt++) {
            sP[(g    )*PPW + nt*8 + pc0] = f2tf32(sc[nt][0]);
            sP[(g    )*PPW + nt*8 + pc1] = f2tf32(sc[nt][1]);
            sP[(g + 8)*PPW + nt*8 + pc0] = f2tf32(sc[nt][2]);
            sP[(g + 8)*PPW + nt*8 + pc1] = f2tf32(sc[nt][3]);
        }
        __syncwarp();

        if (tt + 1 < SS/64) cp_wait<1>();   // V(tt) done (K(tt+1) pending)
        else                cp_wait<0>();
        __syncthreads();
        if (tt + 1 < SS/64)
            issueV(Vb, sm + A_OFF_V + ((tt+1)&1)*64*VP, (tt+1)*64, tid);

        // ---- PV: paired P loads (conflict-free), scalar V loads ----
        #pragma unroll
        for (int ks = 0; ks < 8; ks++) {
            float2 plo = *(const float2*)&sP[(g    )*PPW + ks*8 + 2*t];
            float2 phi = *(const float2*)&sP[(g + 8)*PPW + ks*8 + 2*t];
            unsigned pa[4];
            pa[0] = __float_as_uint(plo.x);
            pa[2] = __float_as_uint(plo.y);
            pa[1] = __float_as_uint(phi.x);
            pa[3] = __float_as_uint(phi.y);
            #pragma unroll
            for (int nt = 0; nt < 10; nt++) {
                unsigned bb[2];
                bb[0] = __float_as_uint(sV[(ks*8 + t    )*VP + nt*8 + g]);
                bb[1] = __float_as_uint(sV[(ks*8 + t + 4)*VP + nt*8 + g]);
                mma_tf32(O[nt], pa, bb);
            }
        }
    }

    // ---- epilogue: normalize + tf32-round + perm8 store ----
    float inv0 = 1.f / l0, inv1 = 1.f / l1;
    int s0r = q0 + wr + g, s1r = s0r + 8;
    #pragma unroll
    for (int nt = 0; nt < 10; nt++) {
        int base_c = h*DK + nt*8;
        float* row0 = g_att + ((size_t)b*SS + s0r)*DM + base_c;
        float* row1 = g_att + ((size_t)b*SS + s1r)*DM + base_c;
        row0[pc0] = f2tf32(O[nt][0]*inv0);
        row0[pc1] = f2tf32(O[nt][1]*inv0);
        row1[pc0] = f2tf32(O[nt][2]*inv1);
        row1[pc1] = f2tf32(O[nt][3]*inv1);
    }
}

// ============================================================
// Kernel 3: out = A @ Wo^T + bo, single-pass tf32
// 128x160 tiles -> 256 CTAs = one wave at occ 2.
// GSF=40 (≡8 mod 32): conflict-free paired fragment loads.
// ============================================================
#define GSF 40
#define GA1 (128*GSF)
#define GB1 (160*GSF)
#define GEMM_SMEM_FLOATS (2*GA1 + 2*GB1)   // 92.2 KB

__device__ __forceinline__ void gemm_issue(float* gsm, int m0, int n0, int kc, int tid)
{
    const int buf = kc & 1;
    float* sA = gsm + buf*GA1;
    float* sB = gsm + 2*GA1 + buf*GB1;
    #pragma unroll
    for (int p = 0; p < 4; p++) {          // A: 128 rows x 8 segs
        int idx = tid + p*256;
        int r = idx >> 3, seg = idx & 7;
        cp16(smem_u32(sA + r*GSF + seg*4), g_att + (size_t)(m0 + r)*DM + kc*32 + seg*4);
    }
    #pragma unroll
    for (int p = 0; p < 5; p++) {          // B: 160 rows x 8 segs
        int idx = tid + p*256;
        int r = idx >> 3, seg = idx & 7;
        cp16(smem_u32(sB + r*GSF + seg*4), g_wo + (size_t)(n0 + r)*DM + kc*32 + seg*4);
    }
    cp_commit();
}

__global__ __launch_bounds__(256, 2) void out_gemm(
    const float* __restrict__ bo, float* __restrict__ out)
{
    extern __shared__ float gsm[];

    const int m0 = blockIdx.y * 128, n0 = blockIdx.x * 160;
    const int tid = threadIdx.x;
    const int warp = tid >> 5, lane = tid & 31;
    const int g = lane >> 2, t = lane & 3;
    const int wm = warp >> 2, wn = warp & 3;   // 2 x 4 warps, 64x40 tiles

    float acc[4][5][4];
    #pragma unroll
    for (int mt = 0; mt < 4; mt++)
        #pragma unroll
        for (int nt = 0; nt < 5; nt++)
            #pragma unroll
            for (int j = 0; j < 4; j++) acc[mt][nt][j] = 0.f;

    gemm_issue(gsm, m0, n0, 0, tid);
    gemm_issue(gsm, m0, n0, 1, tid);

    for (int kc = 0; kc < DM/32; kc++) {
        if (kc + 1 < DM/32) cp_wait<1>();
        else                cp_wait<0>();
        __syncthreads();

        const float* sA = gsm + (kc & 1)*GA1;
        const float* sB = gsm + 2*GA1 + (kc & 1)*GB1;

        #pragma unroll
        for (int kk = 0; kk < 4; kk++) {
            unsigned fb[5][2];
            #pragma unroll
            for (int nt = 0; nt < 5; nt++) {
                int br = wn*40 + nt*8 + g;
                float2 bv = *(const float2*)&sB[br*GSF + kk*8 + 2*t];
                fb[nt][0] = __float_as_uint(bv.x);
                fb[nt][1] = __float_as_uint(bv.y);
            }
            #pragma unroll
            for (int mt = 0; mt < 4; mt++) {
                int mr = wm*64 + mt*16 + g;
                float2 alo = *(const float2*)&sA[ mr     *GSF + kk*8 + 2*t];
                float2 ahi = *(const float2*)&sA[(mr + 8)*GSF + kk*8 + 2*t];
                unsigned fa[4] = {__float_as_uint(alo.x), __float_as_uint(ahi.x),
                                  __float_as_uint(alo.y), __float_as_uint(ahi.y)};
                #pragma unroll
                for (int nt = 0; nt < 5; nt++)
                    mma_tf32(acc[mt][nt], fa, fb[nt]);
            }
        }
        __syncthreads();
        if (kc + 2 < DM/32)
            gemm_issue(gsm, m0, n0, kc + 2, tid);
    }

    #pragma unroll
    for (int mt = 0; mt < 4; mt++) {
        int r0 = m0 + wm*64 + mt*16 + g;
        #pragma unroll
        for (int nt = 0; nt < 5; nt++) {
            int c0 = n0 + wn*40 + nt*8 + 2*t;
            float2 b2 = *(const float2*)&bo[c0];
            float2 v0 = make_float2(acc[mt][nt][0] + b2.x, acc[mt][nt][1] + b2.y);
            float2 v1 = make_float2(acc[mt][nt][2] + b2.x, acc[mt][nt][3] + b2.y);
            *(float2*)&out[(size_t)r0*DM + c0] = v0;
            *(float2*)&out[(size_t)(r0 + 8)*DM + c0] = v1;
        }
    }
}

// ============================================================
extern "C" void kernel_launch(void* const* d_in, const int* in_sizes, int n_in,
                              void* d_out, int out_size)
{
    const float* src = (const float*)d_in[0];
    const float* Wq = (const float*)d_in[3];
    const float* bq = (const float*)d_in[4];
    const float* Wk = (const float*)d_in[5];
    const float* bk = (const float*)d_in[6];
    const float* Wv = (const float*)d_in[7];
    const float* bv = (const float*)d_in[8];
    const float* Wo = (const float*)d_in[9];
    const float* bo = (const float*)d_in[10];
    float* out = (float*)d_out;

    const int smem_qkv  = QKV_SMEM_FLOATS * (int)sizeof(float);
    const int smem_attn = ATTN_SMEM_FLOATS * (int)sizeof(float);
    const int smem_gemm = GEMM_SMEM_FLOATS * (int)sizeof(float);
    cudaFuncSetAttribute(qkv_kernel, cudaFuncAttributeMaxDynamicSharedMemorySize, smem_qkv);
    cudaFuncSetAttribute(attn_kernel, cudaFuncAttributeMaxDynamicSharedMemorySize, smem_attn);
    cudaFuncSetAttribute(out_gemm, cudaFuncAttributeMaxDynamicSharedMemorySize, smem_gemm);

    wo_round_kernel<<<(DM*(DM/4) + 255)/256, 256>>>(Wo);
    qkv_kernel<<<dim3(SS/128, NH, BB), 256, smem_qkv>>>(src, Wq, bq, Wk, bk, Wv, bv);
    attn_kernel<<<dim3(SS/128, NH, BB), 256, smem_attn>>>();
    out_gemm<<<dim3(DM/160, (BB*SS)/128), 256, smem_gemm>>>(bo, out);
}

// round 14
// speedup vs baseline: 1.7933x; 1.0925x over previous
#include <cuda_runtime.h>
#include <math.h>

#define BB 4
#define SS 1024
#define DM 1280
#define NH 16
#define DK 80
#define GR 5
#define CPG 256

// ---- scratch (device globals; no allocations allowed) ----
__device__ float g_q[(size_t)BB*NH*SS*DK];
__device__ float g_k[(size_t)BB*NH*SS*DK];
__device__ float g_v[(size_t)BB*NH*SS*DK];
__device__ float g_att[(size_t)BB*SS*DM];   // tf32-rounded, perm8 cols
__device__ float g_wo[(size_t)DM*DM];       // tf32-rounded, perm8 cols

// ---- helpers ----
__device__ __forceinline__ float f2tf32(float x) {
    unsigned u;
    asm("cvt.rna.tf32.f32 %0, %1;" : "=r"(u) : "f"(x));
    return __uint_as_float(u);
}
__device__ __forceinline__ void mma_tf32(float d[4], const unsigned a[4], const unsigned b[2]) {
    asm volatile(
        "mma.sync.aligned.m16n8k8.row.col.f32.tf32.tf32.f32 "
        "{%0,%1,%2,%3}, {%4,%5,%6,%7}, {%8,%9}, {%0,%1,%2,%3};\n"
        : "+f"(d[0]), "+f"(d[1]), "+f"(d[2]), "+f"(d[3])
        : "r"(a[0]), "r"(a[1]), "r"(a[2]), "r"(a[3]), "r"(b[0]), "r"(b[1]));
}
__device__ __forceinline__ unsigned smem_u32(const void* p) {
    return (unsigned)__cvta_generic_to_shared(p);
}
__device__ __forceinline__ void cp16(unsigned s, const void* g) {
    asm volatile("cp.async.cg.shared.global [%0], [%1], 16;" :: "r"(s), "l"(g));
}
__device__ __forceinline__ void cp_commit() { asm volatile("cp.async.commit_group;"); }
template<int N> __device__ __forceinline__ void cp_wait() {
    asm volatile("cp.async.wait_group %0;" :: "n"(N));
}
// column pairing within 8-group: (t, t+4) -> adjacent (2t, 2t+1)
__device__ __forceinline__ int perm8(int c) {
    return (c & ~7) | ((c & 3) << 1) | ((c >> 2) & 1);
}

// ============================================================
// Kernel 0: round Wo to tf32 and store with perm8 column layout
// ============================================================
__global__ __launch_bounds__(256) void wo_round_kernel(const float* __restrict__ Wo)
{
    int i = blockIdx.x * 256 + threadIdx.x;    // over DM*DM/4 float4s
    if (i >= DM * (DM/4)) return;
    int n = i / (DM/4), k4 = (i % (DM/4)) * 4;
    float4 v = *(const float4*)&Wo[(size_t)n*DM + k4];
    int blk = k4 & ~7, off = k4 & 7;           // off = 0 or 4
    float* dst = g_wo + (size_t)n*DM + blk;
    dst[perm8(off    )] = f2tf32(v.x);
    dst[perm8(off + 1)] = f2tf32(v.y);
    dst[perm8(off + 2)] = f2tf32(v.z);
    dst[perm8(off + 3)] = f2tf32(v.w);
}

// ============================================================
// Kernel 1: channel shuffle + per-head QKV projections
// (unchanged; 1/sqrt(dk) folded into Wq/bq; linear outputs)
// ============================================================
#define XS 84
#define QKV_SMEM_FLOATS (128*XS + 80*XS + 80)

__global__ __launch_bounds__(256) void qkv_kernel(
    const float* __restrict__ src,
    const float* __restrict__ Wq, const float* __restrict__ bq,
    const float* __restrict__ Wk, const float* __restrict__ bk,
    const float* __restrict__ Wv, const float* __restrict__ bv)
{
    extern __shared__ float qsm[];
    float* sX = qsm;              // [128][84]
    float* sW = sX + 128*XS;      // [80][84]
    float* sb = sW + 80*XS;       // [80]

    const int b = blockIdx.z, h = blockIdx.y, s0 = blockIdx.x * 128;
    const int tid = threadIdx.x;
    const int warp = tid >> 5, lane = tid & 31;
    const int g = lane >> 2, t = lane & 3;
    const int wr = warp * 16;

    #pragma unroll
    for (int p = 0; p < 10; p++) {
        int idx = tid + p*256;
        int r = idx / 20, q = idx % 20;
        int j = q / 4, m = q % 4;
        float4 v = *(const float4*)&src[((size_t)b*SS + s0 + r)*DM + j*CPG + 16*h + m*4];
        int kbase = (m*4)*5 + j;
        sX[r*XS + kbase     ] = f2tf32(v.x);
        sX[r*XS + kbase + 5 ] = f2tf32(v.y);
        sX[r*XS + kbase + 10] = f2tf32(v.z);
        sX[r*XS + kbase + 15] = f2tf32(v.w);
    }
    __syncthreads();

    unsigned qa[10][4];
    #pragma unroll
    for (int ks = 0; ks < 10; ks++) {
        qa[ks][0] = __float_as_uint(sX[(wr + g    )*XS + ks*8 + t    ]);
        qa[ks][1] = __float_as_uint(sX[(wr + g + 8)*XS + ks*8 + t    ]);
        qa[ks][2] = __float_as_uint(sX[(wr + g    )*XS + ks*8 + t + 4]);
        qa[ks][3] = __float_as_uint(sX[(wr + g + 8)*XS + ks*8 + t + 4]);
    }

    const float* Ws[3] = {Wq, Wk, Wv};
    const float* bs[3] = {bq, bk, bv};
    float* outs[3] = {g_q, g_k, g_v};
    const float scl = rsqrtf((float)DK);

    for (int pj = 0; pj < 3; pj++) {
        const float s = (pj == 0) ? scl : 1.f;
        __syncthreads();
        for (int i = tid; i < 1600; i += 256) {
            int e = i / 20, k = (i % 20) * 4;
            float4 w = *(const float4*)&Ws[pj][h*DK*DK + e*DK + k];
            float4 wr4 = make_float4(f2tf32(w.x*s), f2tf32(w.y*s), f2tf32(w.z*s), f2tf32(w.w*s));
            *(float4*)&sW[e*XS + k] = wr4;
        }
        if (tid < DK) sb[tid] = bs[pj][h*DK + tid] * s;
        __syncthreads();

        float acc[10][4];
        #pragma unroll
        for (int nt = 0; nt < 10; nt++)
            #pragma unroll
            for (int j = 0; j < 4; j++) acc[nt][j] = 0.f;

        #pragma unroll
        for (int ks = 0; ks < 10; ks++) {
            #pragma unroll
            for (int nt = 0; nt < 10; nt++) {
                unsigned bb[2];
                bb[0] = __float_as_uint(sW[(nt*8 + g)*XS + ks*8 + t    ]);
                bb[1] = __float_as_uint(sW[(nt*8 + g)*XS + ks*8 + t + 4]);
                mma_tf32(acc[nt], qa[ks], bb);
            }
        }

        float* outp = outs[pj] + (((size_t)b*NH + h)*SS + s0) * DK;
        #pragma unroll
        for (int nt = 0; nt < 10; nt++) {
            int c = nt*8 + 2*t;
            float b0 = sb[c], b1 = sb[c + 1];
            float2 v0 = make_float2(f2tf32(acc[nt][0] + b0), f2tf32(acc[nt][1] + b1));
            float2 v1 = make_float2(f2tf32(acc[nt][2] + b0), f2tf32(acc[nt][3] + b1));
            *(float2*)&outp[(size_t)(wr + g    )*DK + c] = v0;
            *(float2*)&outp[(size_t)(wr + g + 8)*DK + c] = v1;
        }
    }
}

// ============================================================
// Kernel 2: flash attention, tf32 mma
// 256-row q tiles, 8 warps x 32 rows; K AND V double-buffered
// -> ONE __syncthreads per kv-tile (warps drift; softmax/MUFU
// overlaps other warps' MMAs). P buffer is 16 rows/warp (PPW=72,
// proven stride); PV split into two m-tile passes reusing it.
// smem 206 KB.
// ============================================================
#define QP 84
#define KP 84
#define VP 88
#define PPW 72
#define A_OFF_Q 0
#define A_OFF_K (256*QP)
#define A_OFF_V (A_OFF_K + 2*64*KP)
#define A_OFF_P (A_OFF_V + 2*64*VP)
#define ATTN_SMEM_FLOATS (A_OFF_P + 8*16*PPW)    // 52736 fl = 206 KB

__device__ __forceinline__ void issueKV(const float* Kb, const float* Vb,
                                        float* sK, float* sV, int kt, int tid)
{
    #pragma unroll
    for (int p = 0; p < 5; p++) {
        int c = tid + p*256;
        int r = c / 20, seg = c % 20;
        cp16(smem_u32(sK + r*KP + seg*4), Kb + (size_t)(kt + r)*DK + seg*4);
    }
    #pragma unroll
    for (int p = 0; p < 5; p++) {
        int c = tid + p*256;
        int r = c / 20, seg = c % 20;
        cp16(smem_u32(sV + r*VP + seg*4), Vb + (size_t)(kt + r)*DK + seg*4);
    }
    cp_commit();
}

__global__ __launch_bounds__(256) void attn_kernel()
{
    extern __shared__ float sm[];
    float* sQ = sm + A_OFF_Q;

    const int b = blockIdx.z, h = blockIdx.y, q0 = blockIdx.x * 256;
    const int tid = threadIdx.x;
    const int warp = tid >> 5, lane = tid & 31;
    const int g = lane >> 2, t = lane & 3;
    const int wr = warp * 32;
    float* sP = sm + A_OFF_P + warp * 16 * PPW;   // warp-private, 16 rows

    const size_t base = ((size_t)b*NH + h) * SS * DK;
    const float* Qb = g_q + base;     // pre-scaled, tf32-rounded
    const float* Kb = g_k + base;
    const float* Vb = g_v + base;

    // stage Q (column-paired): 5120 float4 pieces
    #pragma unroll
    for (int p = 0; p < 20; p++) {
        int idx = tid + p*256;
        int r = idx / 20, q4 = idx % 20;
        float4 v = *(const float4*)&Qb[(size_t)(q0 + r)*DK + q4*4];
        int k = q4*4;
        sQ[r*QP + perm8(k    )] = v.x;
        sQ[r*QP + perm8(k + 1)] = v.y;
        sQ[r*QP + perm8(k + 2)] = v.z;
        sQ[r*QP + perm8(k + 3)] = v.w;
    }
    issueKV(Kb, Vb, sm + A_OFF_K, sm + A_OFF_V, 0, tid);   // group 0

    float O[2][10][4];
    #pragma unroll
    for (int mt = 0; mt < 2; mt++)
        #pragma unroll
        for (int nt = 0; nt < 10; nt++)
            #pragma unroll
            for (int j = 0; j < 4; j++) O[mt][nt][j] = 0.f;
    float mM[2][2], lL[2][2];
    #pragma unroll
    for (int mt = 0; mt < 2; mt++) {
        mM[mt][0] = mM[mt][1] = -1e30f;
        lL[mt][0] = lL[mt][1] = 0.f;
    }

    const int pc0 = ((2*t & 3) << 1) | ((2*t) >> 2);
    const int pc1 = (((2*t+1) & 3) << 1) | ((2*t+1) >> 2);

    for (int tt = 0; tt < SS/64; tt++) {
        float* sK = sm + A_OFF_K + (tt & 1) * 64*KP;
        float* sV = sm + A_OFF_V + (tt & 1) * 64*VP;

        cp_wait<0>();        // tile tt data complete (this thread's shares)
        __syncthreads();     // publish + all warps done with buffers (tt-1)
        if (tt + 1 < SS/64)
            issueKV(Kb, Vb,
                    sm + A_OFF_K + ((tt+1)&1)*64*KP,
                    sm + A_OFF_V + ((tt+1)&1)*64*VP, (tt+1)*64, tid);

        // ---- scores: 32x64 per warp, K B-frags shared by 2 m-tiles ----
        float sc[2][8][4];
        #pragma unroll
        for (int mt = 0; mt < 2; mt++)
            #pragma unroll
            for (int nt = 0; nt < 8; nt++)
                #pragma unroll
                for (int j = 0; j < 4; j++) sc[mt][nt][j] = 0.f;

        #pragma unroll
        for (int ks = 0; ks < 10; ks++) {
            unsigned qa2[2][4];
            #pragma unroll
            for (int mt = 0; mt < 2; mt++) {
                float2 qlo = *(const float2*)&sQ[(wr + mt*16 + g    )*QP + ks*8 + 2*t];
                float2 qhi = *(const float2*)&sQ[(wr + mt*16 + g + 8)*QP + ks*8 + 2*t];
                qa2[mt][0] = __float_as_uint(qlo.x);
                qa2[mt][2] = __float_as_uint(qlo.y);
                qa2[mt][1] = __float_as_uint(qhi.x);
                qa2[mt][3] = __float_as_uint(qhi.y);
            }
            #pragma unroll
            for (int nt = 0; nt < 8; nt++) {
                unsigned bb[2];
                bb[0] = __float_as_uint(sK[(nt*8 + g)*KP + ks*8 + t    ]);
                bb[1] = __float_as_uint(sK[(nt*8 + g)*KP + ks*8 + t + 4]);
                mma_tf32(sc[0][nt], qa2[0], bb);
                mma_tf32(sc[1][nt], qa2[1], bb);
            }
        }

        // ---- per m-tile: softmax -> stage P (16-row buffer) -> PV ----
        #pragma unroll
        for (int mt = 0; mt < 2; mt++) {
            float mx0 = -1e30f, mx1 = -1e30f;
            #pragma unroll
            for (int nt = 0; nt < 8; nt++) {
                mx0 = fmaxf(mx0, fmaxf(sc[mt][nt][0], sc[mt][nt][1]));
                mx1 = fmaxf(mx1, fmaxf(sc[mt][nt][2], sc[mt][nt][3]));
            }
            #pragma unroll
            for (int msk = 1; msk <= 2; msk <<= 1) {
                mx0 = fmaxf(mx0, __shfl_xor_sync(0xffffffffu, mx0, msk));
                mx1 = fmaxf(mx1, __shfl_xor_sync(0xffffffffu, mx1, msk));
            }
            float mn0 = fmaxf(mM[mt][0], mx0), mn1 = fmaxf(mM[mt][1], mx1);
            float a0 = __expf(mM[mt][0] - mn0), a1 = __expf(mM[mt][1] - mn1);
            mM[mt][0] = mn0; mM[mt][1] = mn1;

            float sum0 = 0.f, sum1 = 0.f;
            #pragma unroll
            for (int nt = 0; nt < 8; nt++) {
                sc[mt][nt][0] = __expf(sc[mt][nt][0] - mn0);
                sc[mt][nt][1] = __expf(sc[mt][nt][1] - mn0);
                sc[mt][nt][2] = __expf(sc[mt][nt][2] - mn1);
                sc[mt][nt][3] = __expf(sc[mt][nt][3] - mn1);
                sum0 += sc[mt][nt][0] + sc[mt][nt][1];
                sum1 += sc[mt][nt][2] + sc[mt][nt][3];
            }
            #pragma unroll
            for (int msk = 1; msk <= 2; msk <<= 1) {
                sum0 += __shfl_xor_sync(0xffffffffu, sum0, msk);
                sum1 += __shfl_xor_sync(0xffffffffu, sum1, msk);
            }
            lL[mt][0] = lL[mt][0]*a0 + sum0;
            lL[mt][1] = lL[mt][1]*a1 + sum1;

            #pragma unroll
            for (int nt = 0; nt < 10; nt++) {
                O[mt][nt][0] *= a0; O[mt][nt][1] *= a0;
                O[mt][nt][2] *= a1; O[mt][nt][3] *= a1;
            }

            // stage P(mt) into the 16-row warp buffer
            #pragma unroll
            for (int nt = 0; nt < 8; nt++) {
                sP[(g    )*PPW + nt*8 + pc0] = f2tf32(sc[mt][nt][0]);
                sP[(g    )*PPW + nt*8 + pc1] = f2tf32(sc[mt][nt][1]);
                sP[(g + 8)*PPW + nt*8 + pc0] = f2tf32(sc[mt][nt][2]);
                sP[(g + 8)*PPW + nt*8 + pc1] = f2tf32(sc[mt][nt][3]);
            }
            __syncwarp();

            // PV(mt): O(16x80) += P(16x64) @ V(64x80)
            #pragma unroll
            for (int ks = 0; ks < 8; ks++) {
                float2 plo = *(const float2*)&sP[(g    )*PPW + ks*8 + 2*t];
                float2 phi = *(const float2*)&sP[(g + 8)*PPW + ks*8 + 2*t];
                unsigned pa[4];
                pa[0] = __float_as_uint(plo.x);
                pa[2] = __float_as_uint(plo.y);
                pa[1] = __float_as_uint(phi.x);
                pa[3] = __float_as_uint(phi.y);
                #pragma unroll
                for (int nt = 0; nt < 10; nt++) {
                    unsigned bb[2];
                    bb[0] = __float_as_uint(sV[(ks*8 + t    )*VP + nt*8 + g]);
                    bb[1] = __float_as_uint(sV[(ks*8 + t + 4)*VP + nt*8 + g]);
                    mma_tf32(O[mt][nt], pa, bb);
                }
            }
            __syncwarp();   // PV reads done before mt=1 overwrites sP
        }
    }

    // ---- epilogue: normalize + tf32-round + perm8 store ----
    #pragma unroll
    for (int mt = 0; mt < 2; mt++) {
        float inv0 = 1.f / lL[mt][0], inv1 = 1.f / lL[mt][1];
        int s0r = q0 + wr + mt*16 + g, s1r = s0r + 8;
        #pragma unroll
        for (int nt = 0; nt < 10; nt++) {
            int base_c = h*DK + nt*8;
            float* row0 = g_att + ((size_t)b*SS + s0r)*DM + base_c;
            float* row1 = g_att + ((size_t)b*SS + s1r)*DM + base_c;
            row0[pc0] = f2tf32(O[mt][nt][0]*inv0);
            row0[pc1] = f2tf32(O[mt][nt][1]*inv0);
            row1[pc0] = f2tf32(O[mt][nt][2]*inv1);
            row1[pc1] = f2tf32(O[mt][nt][3]*inv1);
        }
    }
}

// ============================================================
// Kernel 3: out = A @ Wo^T + bo, single-pass tf32
// (unchanged from R12: 128x160 tiles, GSF=40, one wave)
// ============================================================
#define GSF 40
#define GA1 (128*GSF)
#define GB1 (160*GSF)
#define GEMM_SMEM_FLOATS (2*GA1 + 2*GB1)   // 92.2 KB

__device__ __forceinline__ void gemm_issue(float* gsm, int m0, int n0, int kc, int tid)
{
    const int buf = kc & 1;
    float* sA = gsm + buf*GA1;
    float* sB = gsm + 2*GA1 + buf*GB1;
    #pragma unroll
    for (int p = 0; p < 4; p++) {
        int idx = tid + p*256;
        int r = idx >> 3, seg = idx & 7;
        cp16(smem_u32(sA + r*GSF + seg*4), g_att + (size_t)(m0 + r)*DM + kc*32 + seg*4);
    }
    #pragma unroll
    for (int p = 0; p < 5; p++) {
        int idx = tid + p*256;
        int r = idx >> 3, seg = idx & 7;
        cp16(smem_u32(sB + r*GSF + seg*4), g_wo + (size_t)(n0 + r)*DM + kc*32 + seg*4);
    }
    cp_commit();
}

__global__ __launch_bounds__(256, 2) void out_gemm(
    const float* __restrict__ bo, float* __restrict__ out)
{
    extern __shared__ float gsm[];

    const int m0 = blockIdx.y * 128, n0 = blockIdx.x * 160;
    const int tid = threadIdx.x;
    const int warp = tid >> 5, lane = tid & 31;
    const int g = lane >> 2, t = lane & 3;
    const int wm = warp >> 2, wn = warp & 3;   // 2 x 4 warps, 64x40 tiles

    float acc[4][5][4];
    #pragma unroll
    for (int mt = 0; mt < 4; mt++)
        #pragma unroll
        for (int nt = 0; nt < 5; nt++)
            #pragma unroll
            for (int j = 0; j < 4; j++) acc[mt][nt][j] = 0.f;

    gemm_issue(gsm, m0, n0, 0, tid);
    gemm_issue(gsm, m0, n0, 1, tid);

    for (int kc = 0; kc < DM/32; kc++) {
        if (kc + 1 < DM/32) cp_wait<1>();
        else                cp_wait<0>();
        __syncthreads();

        const float* sA = gsm + (kc & 1)*GA1;
        const float* sB = gsm + 2*GA1 + (kc & 1)*GB1;

        #pragma unroll
        for (int kk = 0; kk < 4; kk++) {
            unsigned fb[5][2];
            #pragma unroll
            for (int nt = 0; nt < 5; nt++) {
                int br = wn*40 + nt*8 + g;
                float2 bv = *(const float2*)&sB[br*GSF + kk*8 + 2*t];
                fb[nt][0] = __float_as_uint(bv.x);
                fb[nt][1] = __float_as_uint(bv.y);
            }
            #pragma unroll
            for (int mt = 0; mt < 4; mt++) {
                int mr = wm*64 + mt*16 + g;
                float2 alo = *(const float2*)&sA[ mr     *GSF + kk*8 + 2*t];
                float2 ahi = *(const float2*)&sA[(mr + 8)*GSF + kk*8 + 2*t];
                unsigned fa[4] = {__float_as_uint(alo.x), __float_as_uint(ahi.x),
                                  __float_as_uint(alo.y), __float_as_uint(ahi.y)};
                #pragma unroll
                for (int nt = 0; nt < 5; nt++)
                    mma_tf32(acc[mt][nt], fa, fb[nt]);
            }
        }
        __syncthreads();
        if (kc + 2 < DM/32)
            gemm_issue(gsm, m0, n0, kc + 2, tid);
    }

    #pragma unroll
    for (int mt = 0; mt < 4; mt++) {
        int r0 = m0 + wm*64 + mt*16 + g;
        #pragma unroll
        for (int nt = 0; nt < 5; nt++) {
            int c0 = n0 + wn*40 + nt*8 + 2*t;
            float2 b2 = *(const float2*)&bo[c0];
            float2 v0 = make_float2(acc[mt][nt][0] + b2.x, acc[mt][nt][1] + b2.y);
            float2 v1 = make_float2(acc[mt][nt][2] + b2.x, acc[mt][nt][3] + b2.y);
            *(float2*)&out[(size_t)r0*DM + c0] = v0;
            *(float2*)&out[(size_t)(r0 + 8)*DM + c0] = v1;
        }
    }
}

// ============================================================
extern "C" void kernel_launch(void* const* d_in, const int* in_sizes, int n_in,
                              void* d_out, int out_size)
{
    const float* src = (const float*)d_in[0];
    const float* Wq = (const float*)d_in[3];
    const float* bq = (const float*)d_in[4];
    const float* Wk = (const float*)d_in[5];
    const float* bk = (const float*)d_in[6];
    const float* Wv = (const float*)d_in[7];
    const float* bv = (const float*)d_in[8];
    const float* Wo = (const float*)d_in[9];
    const float* bo = (const float*)d_in[10];
    float* out = (float*)d_out;

    const int smem_qkv  = QKV_SMEM_FLOATS * (int)sizeof(float);
    const int smem_attn = ATTN_SMEM_FLOATS * (int)sizeof(float);
    const int smem_gemm = GEMM_SMEM_FLOATS * (int)sizeof(float);
    cudaFuncSetAttribute(qkv_kernel, cudaFuncAttributeMaxDynamicSharedMemorySize, smem_qkv);
    cudaFuncSetAttribute(attn_kernel, cudaFuncAttributeMaxDynamicSharedMemorySize, smem_attn);
    cudaFuncSetAttribute(out_gemm, cudaFuncAttributeMaxDynamicSharedMemorySize, smem_gemm);

    wo_round_kernel<<<(DM*(DM/4) + 255)/256, 256>>>(Wo);
    qkv_kernel<<<dim3(SS/128, NH, BB), 256, smem_qkv>>>(src, Wq, bq, Wk, bk, Wv, bv);
    attn_kernel<<<dim3(SS/256, NH, BB), 256, smem_attn>>>();
    out_gemm<<<dim3(DM/160, (BB*SS)/128), 256, smem_gemm>>>(bo, out);
}